// round 3
// baseline (speedup 1.0000x reference)
#include <cuda_runtime.h>
#include <math.h>

// ---------------- problem constants ----------------
constexpr int BATCH = 2;
constexpr int SEQ   = 2048;
constexpr int MTOT  = BATCH * SEQ;   // 4096 rows
constexpr int DIM   = 1024;
constexpr int KD    = 64;
constexpr int HID   = 4096;
constexpr int VOCAB = 32000;
constexpr int NH    = 2;
constexpr int TCH   = 32;            // chunk length
constexpr int NCH   = SEQ / TCH;     // 64 chunks per batch

// ---------------- device scratch ----------------
__device__ float g_x[MTOT * DIM];
__device__ float g_q[MTOT * KD];
__device__ float g_k[MTOT * KD];
__device__ float g_v[MTOT * KD];
__device__ float g_attn[MTOT * KD];
__device__ float g_S [BATCH * NCH * KD * KD];
__device__ float g_Sp[BATCH * NCH * KD * KD];
__device__ float g_ks [BATCH * NCH * KD];
__device__ float g_ksp[BATCH * NCH * KD];
__device__ float g_h[(size_t)MTOT * HID];   // MLP hidden; also reused as pre-LN scratch

// ---------------- embedding ----------------
__global__ void k_embed(const int* __restrict__ idx,
                        const float* __restrict__ tok,
                        const float* __restrict__ pos) {
    int i = blockIdx.x;            // token row 0..4095
    int l = i & (SEQ - 1);
    int row = idx[i];
    const float4* t = (const float4*)(tok + (size_t)row * DIM);
    const float4* p = (const float4*)(pos + (size_t)l * DIM);
    float4* o = (float4*)(g_x + (size_t)i * DIM);
    int d = threadIdx.x;           // 256 threads, DIM/4 = 256 float4
    float4 a = t[d], b = p[d];
    o[d] = make_float4(a.x + b.x, a.y + b.y, a.z + b.z, a.w + b.w);
}

// ---------------- fused QKV projection: [4096,1024] @ [1024,64] x3 ----------------
// grid (1, MTOT/128, 3); z selects (Wq->elu+1->g_q), (Wk->elu+1->g_k), (Wv->g_v)
__global__ __launch_bounds__(256)
void k_qkv(const float* __restrict__ Wq, const float* __restrict__ Wk,
           const float* __restrict__ Wv) {
    constexpr int BM = 128, BK = 8, TM = 8, TN = 4;   // 64 cols: 16 thread-cols x 4
    __shared__ float As[BK][BM];
    __shared__ float Bs[BK][KD];

    int z = blockIdx.z;
    const float* Bm = (z == 0) ? Wq : (z == 1) ? Wk : Wv;
    float* C = (z == 0) ? g_q : (z == 1) ? g_k : g_v;

    int tid = threadIdx.x;
    int tr = (tid >> 4) * TM;              // 0..120
    int tc = (tid & 15) * TN;              // 0..60
    int rowBase = blockIdx.y * BM;

    float acc[TM][TN];
#pragma unroll
    for (int i = 0; i < TM; i++)
#pragma unroll
        for (int j = 0; j < TN; j++) acc[i][j] = 0.f;

    int arow = tid >> 1;
    int acol = (tid & 1) * 4;
    const float* Aptr = g_x + (size_t)(rowBase + arow) * DIM + acol;

    for (int k0 = 0; k0 < DIM; k0 += BK) {
        float4 av = *(const float4*)(Aptr + k0);
        As[acol + 0][arow] = av.x;
        As[acol + 1][arow] = av.y;
        As[acol + 2][arow] = av.z;
        As[acol + 3][arow] = av.w;
        if (tid < BK * KD / 4) {           // 128 threads load 8x64 B tile
            int brl = tid >> 4, bcl = (tid & 15) * 4;
            *(float4*)&Bs[brl][bcl] = *(const float4*)(Bm + (size_t)(k0 + brl) * KD + bcl);
        }
        __syncthreads();
#pragma unroll
        for (int kk = 0; kk < BK; kk++) {
            float a[TM], b[TN];
#pragma unroll
            for (int i = 0; i < TM; i++) a[i] = As[kk][tr + i];
#pragma unroll
            for (int j = 0; j < TN; j++) b[j] = Bs[kk][tc + j];
#pragma unroll
            for (int i = 0; i < TM; i++)
#pragma unroll
                for (int j = 0; j < TN; j++) acc[i][j] += a[i] * b[j];
        }
        __syncthreads();
    }

#pragma unroll
    for (int i = 0; i < TM; i++) {
        int r = rowBase + tr + i;
#pragma unroll
        for (int j = 0; j < TN; j++) {
            float v = acc[i][j];
            if (z < 2) v = (v > 0.f) ? (v + 1.f) : __expf(v);  // elu(v)+1
            C[(size_t)r * KD + tc + j] = v;
        }
    }
}

// ---------------- generic SGEMM: C = A[M,K] @ B[K,N] (+epilogue) ----------------
enum { EP_NONE = 0, EP_BIAS = 2, EP_BIAS_GELU = 3, EP_RESADD = 4 };

template <int EP>
__global__ __launch_bounds__(256)
void k_sgemm(const float* __restrict__ A, const float* __restrict__ Bm,
             float* __restrict__ C, int M, int N, int K,
             const float* __restrict__ aux) {
    constexpr int BM = 128, BN = 128, BK = 8, TM = 8, TN = 8;
    __shared__ float As[BK][BM];
    __shared__ float Bs[BK][BN];

    int tid = threadIdx.x;                 // 256 threads
    int tr = (tid >> 4) * TM;
    int tc = (tid & 15) * TN;
    int rowBase = blockIdx.y * BM;
    int colBase = blockIdx.x * BN;

    float acc[TM][TN];
#pragma unroll
    for (int i = 0; i < TM; i++)
#pragma unroll
        for (int j = 0; j < TN; j++) acc[i][j] = 0.f;

    int arow = tid >> 1;
    int acol = (tid & 1) * 4;
    int brl  = tid >> 5;
    int bcl  = (tid & 31) * 4;
    const float* Aptr = A + (size_t)(rowBase + arow) * K + acol;
    int gc = colBase + bcl;

    for (int k0 = 0; k0 < K; k0 += BK) {
        float4 av = *(const float4*)(Aptr + k0);
        As[acol + 0][arow] = av.x;
        As[acol + 1][arow] = av.y;
        As[acol + 2][arow] = av.z;
        As[acol + 3][arow] = av.w;
        *(float4*)&Bs[brl][bcl] = *(const float4*)(Bm + (size_t)(k0 + brl) * N + gc);
        __syncthreads();
#pragma unroll
        for (int kk = 0; kk < BK; kk++) {
            float a[TM], b[TN];
#pragma unroll
            for (int i = 0; i < TM; i++) a[i] = As[kk][tr + i];
#pragma unroll
            for (int j = 0; j < TN; j++) b[j] = Bs[kk][tc + j];
#pragma unroll
            for (int i = 0; i < TM; i++)
#pragma unroll
                for (int j = 0; j < TN; j++) acc[i][j] += a[i] * b[j];
        }
        __syncthreads();
    }

#pragma unroll
    for (int i = 0; i < TM; i++) {
        int r = rowBase + tr + i;
#pragma unroll
        for (int j = 0; j < TN; j++) {
            int c = colBase + tc + j;
            float v = acc[i][j];
            if (EP == EP_BIAS) {
                v += aux[c];
            } else if (EP == EP_BIAS_GELU) {
                v += aux[c];
                v = 0.5f * v * (1.f + erff(v * 0.70710678118654752f));
            } else if (EP == EP_RESADD) {
                v += aux[(size_t)r * N + c];
            }
            C[(size_t)r * N + c] = v;
        }
    }
}

// ---------------- per-chunk KV / K-sum states ----------------
__global__ void k_chunkstate() {        // grid (NCH, BATCH), 256 threads
    int c = blockIdx.x, b = blockIdx.y;
    int base = b * SEQ + c * TCH;
    __shared__ float Ks[TCH][KD], Vs[TCH][KD];
    for (int i = threadIdx.x; i < TCH * KD; i += 256) {
        int t = i >> 6, d = i & 63;
        Ks[t][d] = g_k[(size_t)(base + t) * KD + d];
        Vs[t][d] = g_v[(size_t)(base + t) * KD + d];
    }
    __syncthreads();
    int sidx = b * NCH + c;
    for (int e = threadIdx.x; e < KD * KD; e += 256) {
        int a = e >> 6, v = e & 63;
        float s = 0.f;
#pragma unroll
        for (int t = 0; t < TCH; t++) s += Ks[t][a] * Vs[t][v];
        g_S[(size_t)sidx * KD * KD + e] = s;
    }
    if (threadIdx.x < KD) {
        float s = 0.f;
#pragma unroll
        for (int t = 0; t < TCH; t++) s += Ks[t][threadIdx.x];
        g_ks[sidx * KD + threadIdx.x] = s;
    }
}

// ---------------- exclusive prefix over chunks ----------------
__global__ void k_prefix() {            // grid BATCH, 256 threads
    int b = blockIdx.x;
    for (int i = threadIdx.x; i < KD * KD; i += 256) {
        float run = 0.f;
        for (int c = 0; c < NCH; c++) {
            size_t off = (size_t)(b * NCH + c) * KD * KD + i;
            g_Sp[off] = run;
            run += g_S[off];
        }
    }
    if (threadIdx.x < KD) {
        float run = 0.f;
        for (int c = 0; c < NCH; c++) {
            int off = (b * NCH + c) * KD + threadIdx.x;
            g_ksp[off] = run;
            run += g_ks[off];
        }
    }
}

// ---------------- intra + inter chunk attention ----------------
__global__ __launch_bounds__(256) void k_attn() {  // grid (NCH, BATCH)
    int c = blockIdx.x, b = blockIdx.y;
    int base = b * SEQ + c * TCH;
    int sidx = b * NCH + c;
    __shared__ float Qs[TCH][KD], Ks[TCH][KD], Vs[TCH][KD];
    __shared__ float Sp[KD][KD];
    __shared__ float sc[TCH][TCH];
    __shared__ float dens[TCH];
    __shared__ float ksp[KD];

    for (int i = threadIdx.x; i < TCH * KD; i += 256) {
        int t = i >> 6, d = i & 63;
        Qs[t][d] = g_q[(size_t)(base + t) * KD + d];
        Ks[t][d] = g_k[(size_t)(base + t) * KD + d];
        Vs[t][d] = g_v[(size_t)(base + t) * KD + d];
    }
    for (int i = threadIdx.x; i < KD * KD; i += 256)
        Sp[i >> 6][i & 63] = g_Sp[(size_t)sidx * KD * KD + i];
    if (threadIdx.x < KD) ksp[threadIdx.x] = g_ksp[sidx * KD + threadIdx.x];
    __syncthreads();

    // causal intra-chunk scores
    for (int e = threadIdx.x; e < TCH * TCH; e += 256) {
        int t = e / TCH, s = e % TCH;
        float v = 0.f;
        if (s <= t) {
#pragma unroll
            for (int k = 0; k < KD; k++) v += Qs[t][k] * Ks[s][k];
        }
        sc[t][s] = v;
    }
    __syncthreads();

    if (threadIdx.x < TCH) {
        int t = threadIdx.x;
        float d = 0.f;
        for (int s = 0; s <= t; s++) d += sc[t][s];
#pragma unroll
        for (int k = 0; k < KD; k++) d += Qs[t][k] * ksp[k];
        dens[t] = d + 1e-6f;
    }
    __syncthreads();

    for (int e = threadIdx.x; e < TCH * KD; e += 256) {
        int t = e >> 6, j = e & 63;
        float v = 0.f;
#pragma unroll
        for (int s = 0; s < TCH; s++) v += sc[t][s] * Vs[s][j];
#pragma unroll
        for (int k = 0; k < KD; k++) v += Qs[t][k] * Sp[k][j];
        g_attn[(size_t)(base + t) * KD + j] = v / dens[t];
    }
}

// ---------------- LayerNorm (row of 1024) ----------------
__global__ void k_ln(const float* __restrict__ in, const float* __restrict__ g,
                     const float* __restrict__ b, float* __restrict__ out) {
    int r = blockIdx.x;
    const float* x = in + (size_t)r * DIM;
    __shared__ float red[256];
    int t = threadIdx.x;
    float v[4];
    float s = 0.f;
#pragma unroll
    for (int i = 0; i < 4; i++) { v[i] = x[t + 256 * i]; s += v[i]; }
    red[t] = s;
    __syncthreads();
    for (int o = 128; o > 0; o >>= 1) {
        if (t < o) red[t] += red[t + o];
        __syncthreads();
    }
    float mean = red[0] * (1.f / DIM);
    __syncthreads();
    float q = 0.f;
#pragma unroll
    for (int i = 0; i < 4; i++) { float d = v[i] - mean; q += d * d; }
    red[t] = q;
    __syncthreads();
    for (int o = 128; o > 0; o >>= 1) {
        if (t < o) red[t] += red[t + o];
        __syncthreads();
    }
    float rstd = rsqrtf(red[0] * (1.f / DIM) + 1e-5f);
    float* o = out + (size_t)r * DIM;
#pragma unroll
    for (int i = 0; i < 4; i++) {
        int col = t + 256 * i;
        o[col] = (v[i] - mean) * rstd * g[col] + b[col];
    }
}

// ---------------- launch ----------------
extern "C" void kernel_launch(void* const* d_in, const int* in_sizes, int n_in,
                              void* d_out, int out_size) {
    const int*   idx = (const int*)d_in[0];
    const float* tok = (const float*)d_in[1];
    const float* pos = (const float*)d_in[2];
    const float* Wq  = (const float*)d_in[3];
    const float* Wk  = (const float*)d_in[4];
    const float* Wv  = (const float*)d_in[5];
    const float* Wo  = (const float*)d_in[6];
    const float* ng  = (const float*)d_in[7];
    const float* nb  = (const float*)d_in[8];
    const float* og  = (const float*)d_in[9];
    const float* ob  = (const float*)d_in[10];
    const float* W1  = (const float*)d_in[11];
    const float* b1  = (const float*)d_in[12];
    const float* W2  = (const float*)d_in[13];
    const float* b2  = (const float*)d_in[14];
    float* out = (float*)d_out;

    float *px, *pa, *ph;
    cudaGetSymbolAddress((void**)&px, g_x);
    cudaGetSymbolAddress((void**)&pa, g_attn);
    cudaGetSymbolAddress((void**)&ph, g_h);

    k_embed<<<MTOT, 256>>>(idx, tok, pos);

    for (int layer = 0; layer < NH; layer++) {
        const float* wo = Wo + (size_t)layer * KD * DIM;

        k_qkv<<<dim3(1, MTOT / 128, 3), 256>>>(Wq + (size_t)layer * DIM * KD,
                                               Wk + (size_t)layer * DIM * KD,
                                               Wv + (size_t)layer * DIM * KD);
        k_chunkstate<<<dim3(NCH, BATCH), 256>>>();
        k_prefix<<<BATCH, 256>>>();
        k_attn<<<dim3(NCH, BATCH), 256>>>();

        // y = attn @ Wo + x  (residual fused), into g_h scratch
        k_sgemm<EP_RESADD><<<dim3(DIM / 128, MTOT / 128), 256>>>(pa, wo, ph, MTOT, DIM, KD, px);
        // x = LN(y)
        k_ln<<<MTOT, 256>>>(ph, ng + layer * DIM, nb + layer * DIM, px);
    }

    // final LN into g_h front (then immediately consumed by GEMM1 into g_h is a
    // conflict -> use g_attn?? too small; reuse g_h tail is unsafe. Keep simple:
    // final LN into g_x is wrong (needs source). Use a dedicated region: the
    // first MTOT*DIM floats of g_h hold xn, GEMM1 writes h at offset MTOT*DIM.
    k_ln<<<MTOT, 256>>>(px, og, ob, ph);                        // xn -> g_h[0 : 4M]
    // h = gelu(xn @ W1 + b1) -> out buffer used as scratch? No: write into g_x?
    // g_x is MTOT*DIM = 4M floats but h is MTOT*HID = 16M. Use out (512MB) as
    // scratch for h, then GEMM2 reads it and writes final logits into out... 
    // overlap hazard. Instead: h -> g_h offset region requires 20M floats total;
    // g_h is exactly 16M. Solution: xn lives in g_x? g_x holds LN input. 
    // Simplest safe: xn -> g_attn? too small. Keep xn in g_h[0:4M] and write h
    // into g_h[? ] impossible. => put xn in g_x AFTER copying: LN reads px and
    // writes ph (done above); copy ph->px via k_copy, then GEMM1 px->ph.
    cudaMemcpyAsync(px, ph, (size_t)MTOT * DIM * sizeof(float), cudaMemcpyDeviceToDevice);
    // h = gelu(xn @ W1 + b1)
    k_sgemm<EP_BIAS_GELU><<<dim3(HID / 128, MTOT / 128), 256>>>(px, W1, ph, MTOT, HID, DIM, b1);
    // logits = h @ W2 + b2
    k_sgemm<EP_BIAS><<<dim3(VOCAB / 128, MTOT / 128), 256>>>(ph, W2, out, MTOT, VOCAB, HID, b2);
}

// round 4
// speedup vs baseline: 3.0230x; 3.0230x over previous
#include <cuda_runtime.h>
#include <math.h>
#include <stdint.h>

// ---------------- problem constants ----------------
constexpr int BATCH = 2;
constexpr int SEQ   = 2048;
constexpr int MTOT  = BATCH * SEQ;   // 4096 rows
constexpr int DIM   = 1024;
constexpr int KD    = 64;
constexpr int HID   = 4096;
constexpr int VOCAB = 32000;
constexpr int NH    = 2;
constexpr int TCH   = 32;            // chunk length
constexpr int NCH   = SEQ / TCH;     // 64 chunks per batch

// ---------------- device scratch ----------------
__device__ float g_x[MTOT * DIM];
__device__ float g_q[MTOT * KD];
__device__ float g_k[MTOT * KD];
__device__ float g_v[MTOT * KD];
__device__ float g_attn[MTOT * KD];
__device__ float g_S [BATCH * NCH * KD * KD];
__device__ float g_Sp[BATCH * NCH * KD * KD];
__device__ float g_ks [BATCH * NCH * KD];
__device__ float g_ksp[BATCH * NCH * KD];
__device__ float g_h[(size_t)MTOT * HID];   // MLP hidden; also pre-LN scratch

__device__ __forceinline__ float gelu_f(float v) {
    return 0.5f * v * (1.f + erff(v * 0.70710678118654752f));
}

// ---------------- embedding ----------------
__global__ void k_embed(const int* __restrict__ idx,
                        const float* __restrict__ tok,
                        const float* __restrict__ pos) {
    int i = blockIdx.x;
    int l = i & (SEQ - 1);
    int row = idx[i];
    const float4* t = (const float4*)(tok + (size_t)row * DIM);
    const float4* p = (const float4*)(pos + (size_t)l * DIM);
    float4* o = (float4*)(g_x + (size_t)i * DIM);
    int d = threadIdx.x;
    float4 a = t[d], b = p[d];
    o[d] = make_float4(a.x + b.x, a.y + b.y, a.z + b.z, a.w + b.w);
}

// ---------------- fused QKV projection ----------------
__global__ __launch_bounds__(256)
void k_qkv(const float* __restrict__ Wq, const float* __restrict__ Wk,
           const float* __restrict__ Wv) {
    constexpr int BM = 128, BK = 8, TM = 8, TN = 4;
    __shared__ float As[BK][BM];
    __shared__ float Bs[BK][KD];

    int z = blockIdx.z;
    const float* Bm = (z == 0) ? Wq : (z == 1) ? Wk : Wv;
    float* C = (z == 0) ? g_q : (z == 1) ? g_k : g_v;

    int tid = threadIdx.x;
    int tr = (tid >> 4) * TM;
    int tc = (tid & 15) * TN;
    int rowBase = blockIdx.y * BM;

    float acc[TM][TN];
#pragma unroll
    for (int i = 0; i < TM; i++)
#pragma unroll
        for (int j = 0; j < TN; j++) acc[i][j] = 0.f;

    int arow = tid >> 1;
    int acol = (tid & 1) * 4;
    const float* Aptr = g_x + (size_t)(rowBase + arow) * DIM + acol;

    for (int k0 = 0; k0 < DIM; k0 += BK) {
        float4 av = *(const float4*)(Aptr + k0);
        As[acol + 0][arow] = av.x;
        As[acol + 1][arow] = av.y;
        As[acol + 2][arow] = av.z;
        As[acol + 3][arow] = av.w;
        if (tid < BK * KD / 4) {
            int brl = tid >> 4, bcl = (tid & 15) * 4;
            *(float4*)&Bs[brl][bcl] = *(const float4*)(Bm + (size_t)(k0 + brl) * KD + bcl);
        }
        __syncthreads();
#pragma unroll
        for (int kk = 0; kk < BK; kk++) {
            float a[TM], b[TN];
#pragma unroll
            for (int i = 0; i < TM; i++) a[i] = As[kk][tr + i];
#pragma unroll
            for (int j = 0; j < TN; j++) b[j] = Bs[kk][tc + j];
#pragma unroll
            for (int i = 0; i < TM; i++)
#pragma unroll
                for (int j = 0; j < TN; j++) acc[i][j] += a[i] * b[j];
        }
        __syncthreads();
    }

#pragma unroll
    for (int i = 0; i < TM; i++) {
        int r = rowBase + tr + i;
#pragma unroll
        for (int j = 0; j < TN; j++) {
            float v = acc[i][j];
            if (z < 2) v = (v > 0.f) ? (v + 1.f) : __expf(v);
            C[(size_t)r * KD + tc + j] = v;
        }
    }
}

// ---------------- SIMT SGEMM (small GEMMs: Wo with residual) ----------------
enum { EP_BIAS = 2, EP_BIAS_GELU = 3, EP_RESADD = 4 };

template <int EP>
__global__ __launch_bounds__(256)
void k_sgemm(const float* __restrict__ A, const float* __restrict__ Bm,
             float* __restrict__ C, int M, int N, int K,
             const float* __restrict__ aux) {
    constexpr int BM = 128, BN = 128, BK = 8, TM = 8, TN = 8;
    __shared__ float As[BK][BM];
    __shared__ float Bs[BK][BN];

    int tid = threadIdx.x;
    int tr = (tid >> 4) * TM;
    int tc = (tid & 15) * TN;
    int rowBase = blockIdx.y * BM;
    int colBase = blockIdx.x * BN;

    float acc[TM][TN];
#pragma unroll
    for (int i = 0; i < TM; i++)
#pragma unroll
        for (int j = 0; j < TN; j++) acc[i][j] = 0.f;

    int arow = tid >> 1;
    int acol = (tid & 1) * 4;
    int brl  = tid >> 5;
    int bcl  = (tid & 31) * 4;
    const float* Aptr = A + (size_t)(rowBase + arow) * K + acol;
    int gc = colBase + bcl;

    for (int k0 = 0; k0 < K; k0 += BK) {
        float4 av = *(const float4*)(Aptr + k0);
        As[acol + 0][arow] = av.x;
        As[acol + 1][arow] = av.y;
        As[acol + 2][arow] = av.z;
        As[acol + 3][arow] = av.w;
        *(float4*)&Bs[brl][bcl] = *(const float4*)(Bm + (size_t)(k0 + brl) * N + gc);
        __syncthreads();
#pragma unroll
        for (int kk = 0; kk < BK; kk++) {
            float a[TM], b[TN];
#pragma unroll
            for (int i = 0; i < TM; i++) a[i] = As[kk][tr + i];
#pragma unroll
            for (int j = 0; j < TN; j++) b[j] = Bs[kk][tc + j];
#pragma unroll
            for (int i = 0; i < TM; i++)
#pragma unroll
                for (int j = 0; j < TN; j++) acc[i][j] += a[i] * b[j];
        }
        __syncthreads();
    }

#pragma unroll
    for (int i = 0; i < TM; i++) {
        int r = rowBase + tr + i;
#pragma unroll
        for (int j = 0; j < TN; j++) {
            int c = colBase + tc + j;
            float v = acc[i][j];
            if (EP == EP_BIAS) v += aux[c];
            else if (EP == EP_BIAS_GELU) v = gelu_f(v + aux[c]);
            else if (EP == EP_RESADD) v += aux[(size_t)r * N + c];
            C[(size_t)r * N + c] = v;
        }
    }
}

// ---------------- tf32 tensor-core GEMM: C = A[M,K] @ B[K,N] (+epilogue) ----------------
// 128x128x32 block tile, 8 warps x (64x32) warp tile, mma.sync m16n8k8 tf32,
// cp.async double-buffered smem. Grid: (M/128, N/128) — row-block fastest so a
// wave of blocks shares each B column slice through L2.
constexpr int TBM = 128, TBN = 128, TBK = 32;
constexpr int AS_LD = TBK + 4;    // 36 floats/row (A stored [m][k])
constexpr int BS_LD = TBN + 8;    // 136 floats/row (B stored [k][n])
constexpr int AS_SZ = TBM * AS_LD;  // 4608 floats per buffer
constexpr int BS_SZ = TBK * BS_LD;  // 4352
constexpr int TSMEM_BYTES = (2 * AS_SZ + 2 * BS_SZ) * 4;  // 71680

__device__ __forceinline__ uint32_t f2tf32(float x) {
    uint32_t r;
    asm("cvt.rna.tf32.f32 %0, %1;" : "=r"(r) : "f"(x));
    return r;
}
__device__ __forceinline__ void cp16(float* dst, const float* src) {
    uint32_t sa = (uint32_t)__cvta_generic_to_shared(dst);
    asm volatile("cp.async.cg.shared.global [%0], [%1], 16;" :: "r"(sa), "l"(src));
}

template <int EP>
__global__ __launch_bounds__(256)
void k_tgemm(const float* __restrict__ A, const float* __restrict__ Bm,
             float* __restrict__ C, int M, int N, int K,
             const float* __restrict__ aux) {
    extern __shared__ float smem[];
    float* AsBuf = smem;                    // 2 * AS_SZ
    float* BsBuf = smem + 2 * AS_SZ;        // 2 * BS_SZ

    int tid  = threadIdx.x;
    int warp = tid >> 5, lane = tid & 31;
    int wm = warp >> 2, wn = warp & 3;      // 2 x 4 warp grid
    int g = lane >> 2, tig = lane & 3;
    int rowBase = blockIdx.x * TBM;
    int colBase = blockIdx.y * TBN;

    // copy indices
    int a_row = tid >> 1;                   // 0..127
    int a_seg = (tid & 1) * 4;              // float4 index base 0 or 4
    int b_row = tid >> 3;                   // 0..31
    int b_c4  = (tid & 7);                  // float4 col base

    float acc[4][4][4];
#pragma unroll
    for (int mt = 0; mt < 4; mt++)
#pragma unroll
        for (int nt = 0; nt < 4; nt++)
#pragma unroll
            for (int e = 0; e < 4; e++) acc[mt][nt][e] = 0.f;

    const float* Arow = A + (size_t)(rowBase + a_row) * K;

    auto load_tiles = [&](int k0, int buf) {
        float* as = AsBuf + buf * AS_SZ;
        float* bs = BsBuf + buf * BS_SZ;
#pragma unroll
        for (int i = 0; i < 4; i++) {
            int c4 = a_seg + i;             // 0..7
            cp16(as + a_row * AS_LD + c4 * 4, Arow + k0 + c4 * 4);
        }
        const float* Brow = Bm + (size_t)(k0 + b_row) * N + colBase;
#pragma unroll
        for (int i = 0; i < 4; i++) {
            int c4 = b_c4 + 8 * i;          // 0..31
            cp16(bs + b_row * BS_LD + c4 * 4, Brow + c4 * 4);
        }
    };

    int NK = K / TBK;
    load_tiles(0, 0);
    asm volatile("cp.async.commit_group;" ::: "memory");

    for (int it = 0; it < NK; it++) {
        if (it + 1 < NK) {
            load_tiles((it + 1) * TBK, (it + 1) & 1);
            asm volatile("cp.async.commit_group;" ::: "memory");
            asm volatile("cp.async.wait_group 1;" ::: "memory");
        } else {
            asm volatile("cp.async.wait_group 0;" ::: "memory");
        }
        __syncthreads();

        const float* as = AsBuf + (it & 1) * AS_SZ;
        const float* bs = BsBuf + (it & 1) * BS_SZ;
#pragma unroll
        for (int ks = 0; ks < 4; ks++) {
            int kb = ks * 8;
            uint32_t af[4][4];
#pragma unroll
            for (int mt = 0; mt < 4; mt++) {
                int r0 = wm * 64 + mt * 16 + g;
                af[mt][0] = f2tf32(as[r0 * AS_LD + kb + tig]);
                af[mt][1] = f2tf32(as[(r0 + 8) * AS_LD + kb + tig]);
                af[mt][2] = f2tf32(as[r0 * AS_LD + kb + tig + 4]);
                af[mt][3] = f2tf32(as[(r0 + 8) * AS_LD + kb + tig + 4]);
            }
            uint32_t bf[4][2];
#pragma unroll
            for (int nt = 0; nt < 4; nt++) {
                int c0 = wn * 32 + nt * 8 + g;
                bf[nt][0] = f2tf32(bs[(kb + tig) * BS_LD + c0]);
                bf[nt][1] = f2tf32(bs[(kb + tig + 4) * BS_LD + c0]);
            }
#pragma unroll
            for (int mt = 0; mt < 4; mt++)
#pragma unroll
                for (int nt = 0; nt < 4; nt++) {
                    asm volatile(
                        "mma.sync.aligned.m16n8k8.row.col.f32.tf32.tf32.f32 "
                        "{%0,%1,%2,%3}, {%4,%5,%6,%7}, {%8,%9}, {%0,%1,%2,%3};"
                        : "+f"(acc[mt][nt][0]), "+f"(acc[mt][nt][1]),
                          "+f"(acc[mt][nt][2]), "+f"(acc[mt][nt][3])
                        : "r"(af[mt][0]), "r"(af[mt][1]), "r"(af[mt][2]), "r"(af[mt][3]),
                          "r"(bf[nt][0]), "r"(bf[nt][1]));
                }
        }
        __syncthreads();
    }

    // epilogue: c0,c1 -> (row, col..col+1); c2,c3 -> (row+8, ...)
#pragma unroll
    for (int mt = 0; mt < 4; mt++) {
        int row = rowBase + wm * 64 + mt * 16 + g;
#pragma unroll
        for (int nt = 0; nt < 4; nt++) {
            int col = colBase + wn * 32 + nt * 8 + 2 * tig;
            float v0 = acc[mt][nt][0], v1 = acc[mt][nt][1];
            float v2 = acc[mt][nt][2], v3 = acc[mt][nt][3];
            if (EP == EP_BIAS) {
                v0 += aux[col]; v1 += aux[col + 1];
                v2 += aux[col]; v3 += aux[col + 1];
            } else if (EP == EP_BIAS_GELU) {
                v0 = gelu_f(v0 + aux[col]); v1 = gelu_f(v1 + aux[col + 1]);
                v2 = gelu_f(v2 + aux[col]); v3 = gelu_f(v3 + aux[col + 1]);
            }
            *(float2*)(C + (size_t)row * N + col)       = make_float2(v0, v1);
            *(float2*)(C + (size_t)(row + 8) * N + col) = make_float2(v2, v3);
        }
    }
}

// ---------------- per-chunk KV / K-sum states ----------------
__global__ void k_chunkstate() {
    int c = blockIdx.x, b = blockIdx.y;
    int base = b * SEQ + c * TCH;
    __shared__ float Ks[TCH][KD], Vs[TCH][KD];
    for (int i = threadIdx.x; i < TCH * KD; i += 256) {
        int t = i >> 6, d = i & 63;
        Ks[t][d] = g_k[(size_t)(base + t) * KD + d];
        Vs[t][d] = g_v[(size_t)(base + t) * KD + d];
    }
    __syncthreads();
    int sidx = b * NCH + c;
    for (int e = threadIdx.x; e < KD * KD; e += 256) {
        int a = e >> 6, v = e & 63;
        float s = 0.f;
#pragma unroll
        for (int t = 0; t < TCH; t++) s += Ks[t][a] * Vs[t][v];
        g_S[(size_t)sidx * KD * KD + e] = s;
    }
    if (threadIdx.x < KD) {
        float s = 0.f;
#pragma unroll
        for (int t = 0; t < TCH; t++) s += Ks[t][threadIdx.x];
        g_ks[sidx * KD + threadIdx.x] = s;
    }
}

// ---------------- exclusive prefix over chunks (parallel over elements) ----------------
__global__ void k_prefix() {            // grid (17, BATCH), 256 threads
    int b = blockIdx.y;
    if (blockIdx.x < 16) {
        int i = blockIdx.x * 256 + threadIdx.x;    // 0..4095
        float run = 0.f;
        for (int c = 0; c < NCH; c++) {
            size_t off = (size_t)(b * NCH + c) * KD * KD + i;
            g_Sp[off] = run;
            run += g_S[off];
        }
    } else if (threadIdx.x < KD) {
        float run = 0.f;
        for (int c = 0; c < NCH; c++) {
            int off = (b * NCH + c) * KD + threadIdx.x;
            g_ksp[off] = run;
            run += g_ks[off];
        }
    }
}

// ---------------- intra + inter chunk attention ----------------
__global__ __launch_bounds__(256) void k_attn() {
    int c = blockIdx.x, b = blockIdx.y;
    int base = b * SEQ + c * TCH;
    int sidx = b * NCH + c;
    __shared__ float Qs[TCH][KD], Ks[TCH][KD], Vs[TCH][KD];
    __shared__ float Sp[KD][KD];
    __shared__ float sc[TCH][TCH];
    __shared__ float dens[TCH];
    __shared__ float ksp[KD];

    for (int i = threadIdx.x; i < TCH * KD; i += 256) {
        int t = i >> 6, d = i & 63;
        Qs[t][d] = g_q[(size_t)(base + t) * KD + d];
        Ks[t][d] = g_k[(size_t)(base + t) * KD + d];
        Vs[t][d] = g_v[(size_t)(base + t) * KD + d];
    }
    for (int i = threadIdx.x; i < KD * KD; i += 256)
        Sp[i >> 6][i & 63] = g_Sp[(size_t)sidx * KD * KD + i];
    if (threadIdx.x < KD) ksp[threadIdx.x] = g_ksp[sidx * KD + threadIdx.x];
    __syncthreads();

    for (int e = threadIdx.x; e < TCH * TCH; e += 256) {
        int t = e / TCH, s = e % TCH;
        float v = 0.f;
        if (s <= t) {
#pragma unroll
            for (int k = 0; k < KD; k++) v += Qs[t][k] * Ks[s][k];
        }
        sc[t][s] = v;
    }
    __syncthreads();

    if (threadIdx.x < TCH) {
        int t = threadIdx.x;
        float d = 0.f;
        for (int s = 0; s <= t; s++) d += sc[t][s];
#pragma unroll
        for (int k = 0; k < KD; k++) d += Qs[t][k] * ksp[k];
        dens[t] = d + 1e-6f;
    }
    __syncthreads();

    for (int e = threadIdx.x; e < TCH * KD; e += 256) {
        int t = e >> 6, j = e & 63;
        float v = 0.f;
#pragma unroll
        for (int s = 0; s < TCH; s++) v += sc[t][s] * Vs[s][j];
#pragma unroll
        for (int k = 0; k < KD; k++) v += Qs[t][k] * Sp[k][j];
        g_attn[(size_t)(base + t) * KD + j] = v / dens[t];
    }
}

// ---------------- LayerNorm (row of 1024) ----------------
__global__ void k_ln(const float* __restrict__ in, const float* __restrict__ g,
                     const float* __restrict__ b, float* __restrict__ out) {
    int r = blockIdx.x;
    const float* x = in + (size_t)r * DIM;
    __shared__ float red[256];
    int t = threadIdx.x;
    float v[4];
    float s = 0.f;
#pragma unroll
    for (int i = 0; i < 4; i++) { v[i] = x[t + 256 * i]; s += v[i]; }
    red[t] = s;
    __syncthreads();
    for (int o = 128; o > 0; o >>= 1) {
        if (t < o) red[t] += red[t + o];
        __syncthreads();
    }
    float mean = red[0] * (1.f / DIM);
    __syncthreads();
    float q = 0.f;
#pragma unroll
    for (int i = 0; i < 4; i++) { float d = v[i] - mean; q += d * d; }
    red[t] = q;
    __syncthreads();
    for (int o = 128; o > 0; o >>= 1) {
        if (t < o) red[t] += red[t + o];
        __syncthreads();
    }
    float rstd = rsqrtf(red[0] * (1.f / DIM) + 1e-5f);
    float* o = out + (size_t)r * DIM;
#pragma unroll
    for (int i = 0; i < 4; i++) {
        int col = t + 256 * i;
        o[col] = (v[i] - mean) * rstd * g[col] + b[col];
    }
}

// ---------------- launch ----------------
extern "C" void kernel_launch(void* const* d_in, const int* in_sizes, int n_in,
                              void* d_out, int out_size) {
    const int*   idx = (const int*)d_in[0];
    const float* tok = (const float*)d_in[1];
    const float* pos = (const float*)d_in[2];
    const float* Wq  = (const float*)d_in[3];
    const float* Wk  = (const float*)d_in[4];
    const float* Wv  = (const float*)d_in[5];
    const float* Wo  = (const float*)d_in[6];
    const float* ng  = (const float*)d_in[7];
    const float* nb  = (const float*)d_in[8];
    const float* og  = (const float*)d_in[9];
    const float* ob  = (const float*)d_in[10];
    const float* W1  = (const float*)d_in[11];
    const float* b1  = (const float*)d_in[12];
    const float* W2  = (const float*)d_in[13];
    const float* b2  = (const float*)d_in[14];
    float* out = (float*)d_out;

    float *px, *pa, *ph;
    cudaGetSymbolAddress((void**)&px, g_x);
    cudaGetSymbolAddress((void**)&pa, g_attn);
    cudaGetSymbolAddress((void**)&ph, g_h);

    cudaFuncSetAttribute(k_tgemm<EP_BIAS>, cudaFuncAttributeMaxDynamicSharedMemorySize, TSMEM_BYTES);
    cudaFuncSetAttribute(k_tgemm<EP_BIAS_GELU>, cudaFuncAttributeMaxDynamicSharedMemorySize, TSMEM_BYTES);

    k_embed<<<MTOT, 256>>>(idx, tok, pos);

    for (int layer = 0; layer < NH; layer++) {
        const float* wo = Wo + (size_t)layer * KD * DIM;

        k_qkv<<<dim3(1, MTOT / 128, 3), 256>>>(Wq + (size_t)layer * DIM * KD,
                                               Wk + (size_t)layer * DIM * KD,
                                               Wv + (size_t)layer * DIM * KD);
        k_chunkstate<<<dim3(NCH, BATCH), 256>>>();
        k_prefix<<<dim3(17, BATCH), 256>>>();
        k_attn<<<dim3(NCH, BATCH), 256>>>();

        // y = attn @ Wo + x  (residual fused), into g_h scratch
        k_sgemm<EP_RESADD><<<dim3(DIM / 128, MTOT / 128), 256>>>(pa, wo, ph, MTOT, DIM, KD, px);
        // x = LN(y)
        k_ln<<<MTOT, 256>>>(ph, ng + layer * DIM, nb + layer * DIM, px);
    }

    // final LN: xn -> g_h front, then copy to g_x so GEMM1 can write h into g_h
    k_ln<<<MTOT, 256>>>(px, og, ob, ph);
    cudaMemcpyAsync(px, ph, (size_t)MTOT * DIM * sizeof(float), cudaMemcpyDeviceToDevice);
    // h = gelu(xn @ W1 + b1)   [tf32 tensor cores]
    k_tgemm<EP_BIAS_GELU><<<dim3(MTOT / TBM, HID / TBN), 256, TSMEM_BYTES>>>(
        px, W1, ph, MTOT, HID, DIM, b1);
    // logits = h @ W2 + b2     [tf32 tensor cores]
    k_tgemm<EP_BIAS><<<dim3(MTOT / TBM, VOCAB / TBN), 256, TSMEM_BYTES>>>(
        ph, W2, out, MTOT, VOCAB, HID, b2);
}

// round 6
// speedup vs baseline: 5.4328x; 1.7971x over previous
#include <cuda_runtime.h>
#include <cuda_fp16.h>
#include <math.h>
#include <stdint.h>

// ---------------- problem constants ----------------
constexpr int BATCH = 2;
constexpr int SEQ   = 2048;
constexpr int MTOT  = BATCH * SEQ;   // 4096 rows
constexpr int DIM   = 1024;
constexpr int KD    = 64;
constexpr int HID   = 4096;
constexpr int VOCAB = 32000;
constexpr int NH    = 2;
constexpr int TCH   = 32;            // chunk length
constexpr int NCH   = SEQ / TCH;     // 64 chunks per batch

// ---------------- device scratch ----------------
__device__ float g_x[MTOT * DIM];
__device__ float g_y[MTOT * DIM];            // pre-LN residual scratch
__device__ float g_q[MTOT * KD];
__device__ float g_k[MTOT * KD];
__device__ float g_v[MTOT * KD];
__device__ float g_attn[MTOT * KD];
__device__ float g_S [BATCH * NCH * KD * KD];
__device__ float g_Sp[BATCH * NCH * KD * KD];
__device__ float g_ks [BATCH * NCH * KD];
__device__ float g_ksp[BATCH * NCH * KD];
__device__ __half g_xh [MTOT * DIM];                 // fp16 xn
__device__ __half g_hh [(size_t)MTOT * HID];         // fp16 hidden
__device__ __half g_w1t[(size_t)HID * DIM];          // W1^T [N,K] fp16
__device__ __half g_w2t[(size_t)VOCAB * HID];        // W2^T [N,K] fp16

__device__ __forceinline__ float gelu_f(float v) {
    return 0.5f * v * (1.f + erff(v * 0.70710678118654752f));
}

// ---------------- embedding ----------------
__global__ void k_embed(const int* __restrict__ idx,
                        const float* __restrict__ tok,
                        const float* __restrict__ pos) {
    int i = blockIdx.x;
    int l = i & (SEQ - 1);
    int row = idx[i];
    const float4* t = (const float4*)(tok + (size_t)row * DIM);
    const float4* p = (const float4*)(pos + (size_t)l * DIM);
    float4* o = (float4*)(g_x + (size_t)i * DIM);
    int d = threadIdx.x;
    float4 a = t[d], b = p[d];
    o[d] = make_float4(a.x + b.x, a.y + b.y, a.z + b.z, a.w + b.w);
}

// ---------------- transpose + fp32->fp16 convert: dst[n][k] = src[k][n] ----------------
__global__ void k_transcvt(const float* __restrict__ src, __half* __restrict__ dst,
                           int K, int N) {
    __shared__ float t[32][33];
    int k0 = blockIdx.y * 32, n0 = blockIdx.x * 32;
    int tx = threadIdx.x, ty = threadIdx.y;          // 32 x 8
#pragma unroll
    for (int i = 0; i < 4; i++)
        t[ty + 8 * i][tx] = src[(size_t)(k0 + ty + 8 * i) * N + n0 + tx];
    __syncthreads();
#pragma unroll
    for (int i = 0; i < 4; i++)
        dst[(size_t)(n0 + ty + 8 * i) * K + k0 + tx] = __float2half(t[tx][ty + 8 * i]);
}

// ---------------- fused QKV projection (fp32 SIMT, small) ----------------
__global__ __launch_bounds__(256)
void k_qkv(const float* __restrict__ Wq, const float* __restrict__ Wk,
           const float* __restrict__ Wv) {
    constexpr int BM = 128, BK = 8, TM = 8, TN = 4;
    __shared__ float As[BK][BM];
    __shared__ float Bs[BK][KD];

    int z = blockIdx.z;
    const float* Bm = (z == 0) ? Wq : (z == 1) ? Wk : Wv;
    float* C = (z == 0) ? g_q : (z == 1) ? g_k : g_v;

    int tid = threadIdx.x;
    int tr = (tid >> 4) * TM;
    int tc = (tid & 15) * TN;
    int rowBase = blockIdx.y * BM;

    float acc[TM][TN];
#pragma unroll
    for (int i = 0; i < TM; i++)
#pragma unroll
        for (int j = 0; j < TN; j++) acc[i][j] = 0.f;

    int arow = tid >> 1;
    int acol = (tid & 1) * 4;
    const float* Aptr = g_x + (size_t)(rowBase + arow) * DIM + acol;

    for (int k0 = 0; k0 < DIM; k0 += BK) {
        float4 av = *(const float4*)(Aptr + k0);
        As[acol + 0][arow] = av.x;
        As[acol + 1][arow] = av.y;
        As[acol + 2][arow] = av.z;
        As[acol + 3][arow] = av.w;
        if (tid < BK * KD / 4) {
            int brl = tid >> 4, bcl = (tid & 15) * 4;
            *(float4*)&Bs[brl][bcl] = *(const float4*)(Bm + (size_t)(k0 + brl) * KD + bcl);
        }
        __syncthreads();
#pragma unroll
        for (int kk = 0; kk < BK; kk++) {
            float a[TM], b[TN];
#pragma unroll
            for (int i = 0; i < TM; i++) a[i] = As[kk][tr + i];
#pragma unroll
            for (int j = 0; j < TN; j++) b[j] = Bs[kk][tc + j];
#pragma unroll
            for (int i = 0; i < TM; i++)
#pragma unroll
                for (int j = 0; j < TN; j++) acc[i][j] += a[i] * b[j];
        }
        __syncthreads();
    }

#pragma unroll
    for (int i = 0; i < TM; i++) {
        int r = rowBase + tr + i;
#pragma unroll
        for (int j = 0; j < TN; j++) {
            float v = acc[i][j];
            if (z < 2) v = (v > 0.f) ? (v + 1.f) : __expf(v);
            C[(size_t)r * KD + tc + j] = v;
        }
    }
}

// ---------------- SIMT SGEMM (Wo with residual, fp32) ----------------
enum { EP_BIAS = 2, EP_BIAS_GELU_H = 3, EP_RESADD = 4 };

template <int EP>
__global__ __launch_bounds__(256)
void k_sgemm(const float* __restrict__ A, const float* __restrict__ Bm,
             float* __restrict__ C, int M, int N, int K,
             const float* __restrict__ aux) {
    constexpr int BM = 128, BN = 128, BK = 8, TM = 8, TN = 8;
    __shared__ float As[BK][BM];
    __shared__ float Bs[BK][BN];

    int tid = threadIdx.x;
    int tr = (tid >> 4) * TM;
    int tc = (tid & 15) * TN;
    int rowBase = blockIdx.y * BM;
    int colBase = blockIdx.x * BN;

    float acc[TM][TN];
#pragma unroll
    for (int i = 0; i < TM; i++)
#pragma unroll
        for (int j = 0; j < TN; j++) acc[i][j] = 0.f;

    int arow = tid >> 1;
    int acol = (tid & 1) * 4;
    int brl  = tid >> 5;
    int bcl  = (tid & 31) * 4;
    const float* Aptr = A + (size_t)(rowBase + arow) * K + acol;
    int gc = colBase + bcl;

    for (int k0 = 0; k0 < K; k0 += BK) {
        float4 av = *(const float4*)(Aptr + k0);
        As[acol + 0][arow] = av.x;
        As[acol + 1][arow] = av.y;
        As[acol + 2][arow] = av.z;
        As[acol + 3][arow] = av.w;
        *(float4*)&Bs[brl][bcl] = *(const float4*)(Bm + (size_t)(k0 + brl) * N + gc);
        __syncthreads();
#pragma unroll
        for (int kk = 0; kk < BK; kk++) {
            float a[TM], b[TN];
#pragma unroll
            for (int i = 0; i < TM; i++) a[i] = As[kk][tr + i];
#pragma unroll
            for (int j = 0; j < TN; j++) b[j] = Bs[kk][tc + j];
#pragma unroll
            for (int i = 0; i < TM; i++)
#pragma unroll
                for (int j = 0; j < TN; j++) acc[i][j] += a[i] * b[j];
        }
        __syncthreads();
    }

#pragma unroll
    for (int i = 0; i < TM; i++) {
        int r = rowBase + tr + i;
#pragma unroll
        for (int j = 0; j < TN; j++) {
            int c = colBase + tc + j;
            float v = acc[i][j];
            if (EP == EP_BIAS) v += aux[c];
            else if (EP == EP_RESADD) v += aux[(size_t)r * N + c];
            C[(size_t)r * N + c] = v;
        }
    }
}

// ============ fp16 tensor-core GEMM: C = A[M,K] @ Bt[N,K]^T (+epilogue) ============
// A, Bt fp16 row-major (K contiguous). 128x128x32 tiles, 8 warps x (64x32),
// mma.sync m16n8k16 fp16 -> fp32 accum, cp.async double buffer.
// Smem rows padded to 40 halves -> conflict-free b32 fragment loads.
constexpr int HBM_ = 128, HBN_ = 128, HBK_ = 32;
constexpr int HLD  = 40;                       // halves per smem row
constexpr int HAS  = HBM_ * HLD;               // 5120 halves per A buffer
constexpr int HBS  = HBN_ * HLD;

__device__ __forceinline__ void cpa16(const __half* src, uint32_t smem_dst) {
    asm volatile("cp.async.cg.shared.global [%0], [%1], 16;" :: "r"(smem_dst), "l"(src));
}

template <int EP>
__global__ __launch_bounds__(256)
void k_hgemm(const __half* __restrict__ A, const __half* __restrict__ Bt,
             void* __restrict__ Cv, int M, int N, int K,
             const float* __restrict__ aux) {
    __shared__ __half As[2][HAS];
    __shared__ __half Bs[2][HBS];

    int tid  = threadIdx.x;
    int warp = tid >> 5, lane = tid & 31;
    int wm = warp >> 2, wn = warp & 3;          // 2 x 4 warp grid -> 64x32 tiles
    int g = lane >> 2, tig = lane & 3;
    int rowBase = blockIdx.x * HBM_;
    int colBase = blockIdx.y * HBN_;

    // copy mapping: thread -> row tid>>1, 16-half segment (tid&1)
    int crow = tid >> 1;
    int cseg = (tid & 1) * 16;                  // halves
    const __half* Arow = A  + (size_t)(rowBase + crow) * K + cseg;
    const __half* Brow = Bt + (size_t)(colBase + crow) * K + cseg;

    float acc[4][4][4];
#pragma unroll
    for (int mt = 0; mt < 4; mt++)
#pragma unroll
        for (int nt = 0; nt < 4; nt++)
#pragma unroll
            for (int e = 0; e < 4; e++) acc[mt][nt][e] = 0.f;

    auto load_tiles = [&](int k0, int buf) {
        uint32_t as = (uint32_t)__cvta_generic_to_shared(&As[buf][crow * HLD + cseg]);
        uint32_t bs = (uint32_t)__cvta_generic_to_shared(&Bs[buf][crow * HLD + cseg]);
        cpa16(Arow + k0,     as);
        cpa16(Arow + k0 + 8, as + 16);
        cpa16(Brow + k0,     bs);
        cpa16(Brow + k0 + 8, bs + 16);
    };

    int NK = K / HBK_;
    load_tiles(0, 0);
    asm volatile("cp.async.commit_group;" ::: "memory");

    for (int it = 0; it < NK; it++) {
        if (it + 1 < NK) {
            load_tiles((it + 1) * HBK_, (it + 1) & 1);
            asm volatile("cp.async.commit_group;" ::: "memory");
            asm volatile("cp.async.wait_group 1;" ::: "memory");
        } else {
            asm volatile("cp.async.wait_group 0;" ::: "memory");
        }
        __syncthreads();

        const __half* as = As[it & 1];
        const __half* bs = Bs[it & 1];
#pragma unroll
        for (int ks = 0; ks < 2; ks++) {
            int kb = ks * 16;
            uint32_t af[4][4];
#pragma unroll
            for (int mt = 0; mt < 4; mt++) {
                int r0 = wm * 64 + mt * 16 + g;
                af[mt][0] = *(const uint32_t*)&as[r0 * HLD + kb + 2 * tig];
                af[mt][1] = *(const uint32_t*)&as[(r0 + 8) * HLD + kb + 2 * tig];
                af[mt][2] = *(const uint32_t*)&as[r0 * HLD + kb + 2 * tig + 8];
                af[mt][3] = *(const uint32_t*)&as[(r0 + 8) * HLD + kb + 2 * tig + 8];
            }
            uint32_t bf[4][2];
#pragma unroll
            for (int nt = 0; nt < 4; nt++) {
                int c0 = wn * 32 + nt * 8 + g;
                bf[nt][0] = *(const uint32_t*)&bs[c0 * HLD + kb + 2 * tig];
                bf[nt][1] = *(const uint32_t*)&bs[c0 * HLD + kb + 2 * tig + 8];
            }
#pragma unroll
            for (int mt = 0; mt < 4; mt++)
#pragma unroll
                for (int nt = 0; nt < 4; nt++) {
                    asm volatile(
                        "mma.sync.aligned.m16n8k16.row.col.f32.f16.f16.f32 "
                        "{%0,%1,%2,%3}, {%4,%5,%6,%7}, {%8,%9}, {%0,%1,%2,%3};"
                        : "+f"(acc[mt][nt][0]), "+f"(acc[mt][nt][1]),
                          "+f"(acc[mt][nt][2]), "+f"(acc[mt][nt][3])
                        : "r"(af[mt][0]), "r"(af[mt][1]), "r"(af[mt][2]), "r"(af[mt][3]),
                          "r"(bf[nt][0]), "r"(bf[nt][1]));
                }
        }
        __syncthreads();
    }

    // epilogue: (c0,c1)->(row, col,col+1); (c2,c3)->(row+8, ...)
#pragma unroll
    for (int mt = 0; mt < 4; mt++) {
        int row = rowBase + wm * 64 + mt * 16 + g;
#pragma unroll
        for (int nt = 0; nt < 4; nt++) {
            int col = colBase + wn * 32 + nt * 8 + 2 * tig;
            float v0 = acc[mt][nt][0], v1 = acc[mt][nt][1];
            float v2 = acc[mt][nt][2], v3 = acc[mt][nt][3];
            if (EP == EP_BIAS) {
                float* C = (float*)Cv;
                v0 += aux[col]; v1 += aux[col + 1];
                v2 += aux[col]; v3 += aux[col + 1];
                *(float2*)(C + (size_t)row * N + col)       = make_float2(v0, v1);
                *(float2*)(C + (size_t)(row + 8) * N + col) = make_float2(v2, v3);
            } else {  // EP_BIAS_GELU_H: fp16 output
                __half* C = (__half*)Cv;
                v0 = gelu_f(v0 + aux[col]); v1 = gelu_f(v1 + aux[col + 1]);
                v2 = gelu_f(v2 + aux[col]); v3 = gelu_f(v3 + aux[col + 1]);
                *(__half2*)(C + (size_t)row * N + col)       = __floats2half2_rn(v0, v1);
                *(__half2*)(C + (size_t)(row + 8) * N + col) = __floats2half2_rn(v2, v3);
            }
        }
    }
}

// ---------------- per-chunk KV / K-sum states ----------------
__global__ void k_chunkstate() {
    int c = blockIdx.x, b = blockIdx.y;
    int base = b * SEQ + c * TCH;
    __shared__ float Ks[TCH][KD], Vs[TCH][KD];
    for (int i = threadIdx.x; i < TCH * KD; i += 256) {
        int t = i >> 6, d = i & 63;
        Ks[t][d] = g_k[(size_t)(base + t) * KD + d];
        Vs[t][d] = g_v[(size_t)(base + t) * KD + d];
    }
    __syncthreads();
    int sidx = b * NCH + c;
    for (int e = threadIdx.x; e < KD * KD; e += 256) {
        int a = e >> 6, v = e & 63;
        float s = 0.f;
#pragma unroll
        for (int t = 0; t < TCH; t++) s += Ks[t][a] * Vs[t][v];
        g_S[(size_t)sidx * KD * KD + e] = s;
    }
    if (threadIdx.x < KD) {
        float s = 0.f;
#pragma unroll
        for (int t = 0; t < TCH; t++) s += Ks[t][threadIdx.x];
        g_ks[sidx * KD + threadIdx.x] = s;
    }
}

// ---------------- exclusive prefix over chunks ----------------
__global__ void k_prefix() {            // grid (17, BATCH), 256 threads
    int b = blockIdx.y;
    if (blockIdx.x < 16) {
        int i = blockIdx.x * 256 + threadIdx.x;
        float run = 0.f;
        for (int c = 0; c < NCH; c++) {
            size_t off = (size_t)(b * NCH + c) * KD * KD + i;
            g_Sp[off] = run;
            run += g_S[off];
        }
    } else if (threadIdx.x < KD) {
        float run = 0.f;
        for (int c = 0; c < NCH; c++) {
            int off = (b * NCH + c) * KD + threadIdx.x;
            g_ksp[off] = run;
            run += g_ks[off];
        }
    }
}

// ---------------- intra + inter chunk attention ----------------
__global__ __launch_bounds__(256) void k_attn() {
    int c = blockIdx.x, b = blockIdx.y;
    int base = b * SEQ + c * TCH;
    int sidx = b * NCH + c;
    __shared__ float Qs[TCH][KD], Ks[TCH][KD], Vs[TCH][KD];
    __shared__ float Sp[KD][KD];
    __shared__ float sc[TCH][TCH];
    __shared__ float dens[TCH];
    __shared__ float ksp[KD];

    for (int i = threadIdx.x; i < TCH * KD; i += 256) {
        int t = i >> 6, d = i & 63;
        Qs[t][d] = g_q[(size_t)(base + t) * KD + d];
        Ks[t][d] = g_k[(size_t)(base + t) * KD + d];
        Vs[t][d] = g_v[(size_t)(base + t) * KD + d];
    }
    for (int i = threadIdx.x; i < KD * KD; i += 256)
        Sp[i >> 6][i & 63] = g_Sp[(size_t)sidx * KD * KD + i];
    if (threadIdx.x < KD) ksp[threadIdx.x] = g_ksp[sidx * KD + threadIdx.x];
    __syncthreads();

    for (int e = threadIdx.x; e < TCH * TCH; e += 256) {
        int t = e / TCH, s = e % TCH;
        float v = 0.f;
        if (s <= t) {
#pragma unroll
            for (int k = 0; k < KD; k++) v += Qs[t][k] * Ks[s][k];
        }
        sc[t][s] = v;
    }
    __syncthreads();

    if (threadIdx.x < TCH) {
        int t = threadIdx.x;
        float d = 0.f;
        for (int s = 0; s <= t; s++) d += sc[t][s];
#pragma unroll
        for (int k = 0; k < KD; k++) d += Qs[t][k] * ksp[k];
        dens[t] = d + 1e-6f;
    }
    __syncthreads();

    for (int e = threadIdx.x; e < TCH * KD; e += 256) {
        int t = e >> 6, j = e & 63;
        float v = 0.f;
#pragma unroll
        for (int s = 0; s < TCH; s++) v += sc[t][s] * Vs[s][j];
#pragma unroll
        for (int k = 0; k < KD; k++) v += Qs[t][k] * Sp[k][j];
        g_attn[(size_t)(base + t) * KD + j] = v / dens[t];
    }
}

// ---------------- LayerNorm (row of 1024), templated output type ----------------
template <typename OutT>
__global__ void k_ln(const float* __restrict__ in, const float* __restrict__ g,
                     const float* __restrict__ b, OutT* __restrict__ out) {
    int r = blockIdx.x;
    const float* x = in + (size_t)r * DIM;
    __shared__ float red[256];
    int t = threadIdx.x;
    float v[4];
    float s = 0.f;
#pragma unroll
    for (int i = 0; i < 4; i++) { v[i] = x[t + 256 * i]; s += v[i]; }
    red[t] = s;
    __syncthreads();
    for (int o = 128; o > 0; o >>= 1) {
        if (t < o) red[t] += red[t + o];
        __syncthreads();
    }
    float mean = red[0] * (1.f / DIM);
    __syncthreads();
    float q = 0.f;
#pragma unroll
    for (int i = 0; i < 4; i++) { float d = v[i] - mean; q += d * d; }
    red[t] = q;
    __syncthreads();
    for (int o = 128; o > 0; o >>= 1) {
        if (t < o) red[t] += red[t + o];
        __syncthreads();
    }
    float rstd = rsqrtf(red[0] * (1.f / DIM) + 1e-5f);
    OutT* o = out + (size_t)r * DIM;
#pragma unroll
    for (int i = 0; i < 4; i++) {
        int col = t + 256 * i;
        float val = (v[i] - mean) * rstd * g[col] + b[col];
        o[col] = (OutT)val;
    }
}

// ---------------- launch ----------------
extern "C" void kernel_launch(void* const* d_in, const int* in_sizes, int n_in,
                              void* d_out, int out_size) {
    const int*   idx = (const int*)d_in[0];
    const float* tok = (const float*)d_in[1];
    const float* pos = (const float*)d_in[2];
    const float* Wq  = (const float*)d_in[3];
    const float* Wk  = (const float*)d_in[4];
    const float* Wv  = (const float*)d_in[5];
    const float* Wo  = (const float*)d_in[6];
    const float* ng  = (const float*)d_in[7];
    const float* nb  = (const float*)d_in[8];
    const float* og  = (const float*)d_in[9];
    const float* ob  = (const float*)d_in[10];
    const float* W1  = (const float*)d_in[11];
    const float* b1  = (const float*)d_in[12];
    const float* W2  = (const float*)d_in[13];
    const float* b2  = (const float*)d_in[14];
    float* out = (float*)d_out;

    float *px, *py, *pa;
    __half *pxh, *phh, *pw1t, *pw2t;
    cudaGetSymbolAddress((void**)&px,  g_x);
    cudaGetSymbolAddress((void**)&py,  g_y);
    cudaGetSymbolAddress((void**)&pa,  g_attn);
    cudaGetSymbolAddress((void**)&pxh, g_xh);
    cudaGetSymbolAddress((void**)&phh, g_hh);
    cudaGetSymbolAddress((void**)&pw1t, g_w1t);
    cudaGetSymbolAddress((void**)&pw2t, g_w2t);

    // one-time weight transposes+converts (part of the graph, ~150us)
    k_transcvt<<<dim3(HID / 32, DIM / 32), dim3(32, 8)>>>(W1, pw1t, DIM, HID);
    k_transcvt<<<dim3(VOCAB / 32, HID / 32), dim3(32, 8)>>>(W2, pw2t, HID, VOCAB);

    k_embed<<<MTOT, 256>>>(idx, tok, pos);

    for (int layer = 0; layer < NH; layer++) {
        const float* wo = Wo + (size_t)layer * KD * DIM;

        k_qkv<<<dim3(1, MTOT / 128, 3), 256>>>(Wq + (size_t)layer * DIM * KD,
                                               Wk + (size_t)layer * DIM * KD,
                                               Wv + (size_t)layer * DIM * KD);
        k_chunkstate<<<dim3(NCH, BATCH), 256>>>();
        k_prefix<<<dim3(17, BATCH), 256>>>();
        k_attn<<<dim3(NCH, BATCH), 256>>>();

        // y = attn @ Wo + x  (residual fused, fp32 SIMT)
        k_sgemm<EP_RESADD><<<dim3(DIM / 128, MTOT / 128), 256>>>(pa, wo, py, MTOT, DIM, KD, px);
        // x = LN(y)
        k_ln<float><<<MTOT, 256>>>(py, ng + layer * DIM, nb + layer * DIM, px);
    }

    // final LN straight to fp16
    k_ln<__half><<<MTOT, 256>>>(px, og, ob, pxh);
    // h = gelu(xn @ W1 + b1)  [fp16 mma, fp16 output]
    k_hgemm<EP_BIAS_GELU_H><<<dim3(MTOT / HBM_, HID / HBN_), 256>>>(
        pxh, pw1t, phh, MTOT, HID, DIM, b1);
    // logits = h @ W2 + b2    [fp16 mma, fp32 output]
    k_hgemm<EP_BIAS><<<dim3(MTOT / HBM_, VOCAB / HBN_), 256>>>(
        phh, pw2t, out, MTOT, VOCAB, HID, b2);
}

// round 8
// speedup vs baseline: 5.6809x; 1.0457x over previous
#include <cuda_runtime.h>
#include <cuda_fp16.h>
#include <math.h>
#include <stdint.h>

// ---------------- problem constants ----------------
constexpr int BATCH = 2;
constexpr int SEQ   = 2048;
constexpr int MTOT  = BATCH * SEQ;   // 4096 rows
constexpr int DIM   = 1024;
constexpr int KD    = 64;
constexpr int HID   = 4096;
constexpr int VOCAB = 32000;
constexpr int NH    = 2;
constexpr int TCH   = 32;            // chunk length
constexpr int NCH   = SEQ / TCH;     // 64 chunks per batch

// ---------------- device scratch ----------------
__device__ float g_x[MTOT * DIM];
__device__ float g_y[MTOT * DIM];            // pre-LN residual scratch
__device__ float g_q[MTOT * KD];
__device__ float g_k[MTOT * KD];
__device__ float g_v[MTOT * KD];
__device__ float g_attn[MTOT * KD];
__device__ float g_S [BATCH * NCH * KD * KD];
__device__ float g_Sp[BATCH * NCH * KD * KD];
__device__ float g_ks [BATCH * NCH * KD];
__device__ float g_ksp[BATCH * NCH * KD];
__device__ __half g_xh [MTOT * DIM];                 // fp16 xn
__device__ __half g_hh [(size_t)MTOT * HID];         // fp16 hidden
__device__ __half g_w1t[(size_t)HID * DIM];          // W1^T [N,K] fp16
__device__ __half g_w2t[(size_t)VOCAB * HID];        // W2^T [N,K] fp16

__device__ __forceinline__ float gelu_f(float v) {
    return 0.5f * v * (1.f + erff(v * 0.70710678118654752f));
}

// ---------------- embedding ----------------
__global__ void k_embed(const int* __restrict__ idx,
                        const float* __restrict__ tok,
                        const float* __restrict__ pos) {
    int i = blockIdx.x;
    int l = i & (SEQ - 1);
    int row = idx[i];
    const float4* t = (const float4*)(tok + (size_t)row * DIM);
    const float4* p = (const float4*)(pos + (size_t)l * DIM);
    float4* o = (float4*)(g_x + (size_t)i * DIM);
    int d = threadIdx.x;
    float4 a = t[d], b = p[d];
    o[d] = make_float4(a.x + b.x, a.y + b.y, a.z + b.z, a.w + b.w);
}

// ---------------- transpose + fp32->fp16 convert: dst[n][k] = src[k][n] ----------------
__global__ void k_transcvt(const float* __restrict__ src, __half* __restrict__ dst,
                           int K, int N) {
    __shared__ float t[32][33];
    int k0 = blockIdx.y * 32, n0 = blockIdx.x * 32;
    int tx = threadIdx.x, ty = threadIdx.y;          // 32 x 8
#pragma unroll
    for (int i = 0; i < 4; i++)
        t[ty + 8 * i][tx] = src[(size_t)(k0 + ty + 8 * i) * N + n0 + tx];
    __syncthreads();
#pragma unroll
    for (int i = 0; i < 4; i++)
        dst[(size_t)(n0 + ty + 8 * i) * K + k0 + tx] = __float2half(t[tx][ty + 8 * i]);
}

// ---------------- fused QKV projection (fp32 SIMT, BM=64 for full-chip grid) ----------------
__global__ __launch_bounds__(256)
void k_qkv(const float* __restrict__ Wq, const float* __restrict__ Wk,
           const float* __restrict__ Wv) {
    constexpr int BM = 64, BK = 8, TM = 4, TN = 4;
    __shared__ float As[BK][BM];
    __shared__ float Bs[BK][KD];

    int z = blockIdx.z;
    const float* Bm = (z == 0) ? Wq : (z == 1) ? Wk : Wv;
    float* C = (z == 0) ? g_q : (z == 1) ? g_k : g_v;

    int tid = threadIdx.x;
    int tr = (tid >> 4) * TM;              // 0..60
    int tc = (tid & 15) * TN;              // 0..60
    int rowBase = blockIdx.y * BM;

    float acc[TM][TN];
#pragma unroll
    for (int i = 0; i < TM; i++)
#pragma unroll
        for (int j = 0; j < TN; j++) acc[i][j] = 0.f;

    int arow = tid >> 2;                   // 0..63
    int acol = (tid & 3) * 2;              // 0,2,4,6
    const float* Aptr = g_x + (size_t)(rowBase + arow) * DIM + acol;

    for (int k0 = 0; k0 < DIM; k0 += BK) {
        float2 av = *(const float2*)(Aptr + k0);
        As[acol + 0][arow] = av.x;
        As[acol + 1][arow] = av.y;
        if (tid < BK * KD / 4) {
            int brl = tid >> 4, bcl = (tid & 15) * 4;
            *(float4*)&Bs[brl][bcl] = *(const float4*)(Bm + (size_t)(k0 + brl) * KD + bcl);
        }
        __syncthreads();
#pragma unroll
        for (int kk = 0; kk < BK; kk++) {
            float a[TM], b[TN];
#pragma unroll
            for (int i = 0; i < TM; i++) a[i] = As[kk][tr + i];
#pragma unroll
            for (int j = 0; j < TN; j++) b[j] = Bs[kk][tc + j];
#pragma unroll
            for (int i = 0; i < TM; i++)
#pragma unroll
                for (int j = 0; j < TN; j++) acc[i][j] += a[i] * b[j];
        }
        __syncthreads();
    }

#pragma unroll
    for (int i = 0; i < TM; i++) {
        int r = rowBase + tr + i;
#pragma unroll
        for (int j = 0; j < TN; j++) {
            float v = acc[i][j];
            if (z < 2) v = (v > 0.f) ? (v + 1.f) : __expf(v);
            C[(size_t)r * KD + tc + j] = v;
        }
    }
}

// ---------------- SIMT SGEMM (Wo with residual, fp32) ----------------
enum { EP_BIAS = 2, EP_BIAS_GELU_H = 3, EP_RESADD = 4 };

template <int EP>
__global__ __launch_bounds__(256)
void k_sgemm(const float* __restrict__ A, const float* __restrict__ Bm,
             float* __restrict__ C, int M, int N, int K,
             const float* __restrict__ aux) {
    constexpr int BM = 128, BN = 128, BK = 8, TM = 8, TN = 8;
    __shared__ float As[BK][BM];
    __shared__ float Bs[BK][BN];

    int tid = threadIdx.x;
    int tr = (tid >> 4) * TM;
    int tc = (tid & 15) * TN;
    int rowBase = blockIdx.y * BM;
    int colBase = blockIdx.x * BN;

    float acc[TM][TN];
#pragma unroll
    for (int i = 0; i < TM; i++)
#pragma unroll
        for (int j = 0; j < TN; j++) acc[i][j] = 0.f;

    int arow = tid >> 1;
    int acol = (tid & 1) * 4;
    int brl  = tid >> 5;
    int bcl  = (tid & 31) * 4;
    const float* Aptr = A + (size_t)(rowBase + arow) * K + acol;
    int gc = colBase + bcl;

    for (int k0 = 0; k0 < K; k0 += BK) {
        float4 av = *(const float4*)(Aptr + k0);
        As[acol + 0][arow] = av.x;
        As[acol + 1][arow] = av.y;
        As[acol + 2][arow] = av.z;
        As[acol + 3][arow] = av.w;
        *(float4*)&Bs[brl][bcl] = *(const float4*)(Bm + (size_t)(k0 + brl) * N + gc);
        __syncthreads();
#pragma unroll
        for (int kk = 0; kk < BK; kk++) {
            float a[TM], b[TN];
#pragma unroll
            for (int i = 0; i < TM; i++) a[i] = As[kk][tr + i];
#pragma unroll
            for (int j = 0; j < TN; j++) b[j] = Bs[kk][tc + j];
#pragma unroll
            for (int i = 0; i < TM; i++)
#pragma unroll
                for (int j = 0; j < TN; j++) acc[i][j] += a[i] * b[j];
        }
        __syncthreads();
    }

#pragma unroll
    for (int i = 0; i < TM; i++) {
        int r = rowBase + tr + i;
#pragma unroll
        for (int j = 0; j < TN; j++) {
            int c = colBase + tc + j;
            float v = acc[i][j];
            if (EP == EP_BIAS) v += aux[c];
            else if (EP == EP_RESADD) v += aux[(size_t)r * N + c];
            C[(size_t)r * N + c] = v;
        }
    }
}

// ============ fp16 tensor-core GEMM: C = A[M,K] @ Bt[N,K]^T (+epilogue) ============
// 128x128x32 tiles, 8 warps x (64x32), mma.sync m16n8k16, fp32 accum.
// ldmatrix.x4 fragment loads (conflict-free with 80B row stride), 3-stage cp.async.
constexpr int HBM_ = 128, HBN_ = 128, HBK_ = 32;
constexpr int HLD  = 40;                       // halves per smem row (80 B)
constexpr int HAS  = HBM_ * HLD;               // 5120 halves
constexpr int HBS  = HBN_ * HLD;               // 5120 halves
constexpr int HSTG = HAS + HBS;                // halves per stage
constexpr int HSMEM_BYTES = 3 * HSTG * 2;      // 61440

__device__ __forceinline__ void cpa16(const __half* src, uint32_t smem_dst) {
    asm volatile("cp.async.cg.shared.global [%0], [%1], 16;" :: "r"(smem_dst), "l"(src));
}
__device__ __forceinline__ void ldsm4(uint32_t& r0, uint32_t& r1, uint32_t& r2, uint32_t& r3,
                                      uint32_t addr) {
    asm volatile("ldmatrix.sync.aligned.m8n8.x4.shared.b16 {%0,%1,%2,%3}, [%4];"
                 : "=r"(r0), "=r"(r1), "=r"(r2), "=r"(r3) : "r"(addr));
}

template <int EP>
__global__ __launch_bounds__(256)
void k_hgemm(const __half* __restrict__ A, const __half* __restrict__ Bt,
             void* __restrict__ Cv, int M, int N, int K,
             const float* __restrict__ aux) {
    extern __shared__ __half hsm[];

    int tid  = threadIdx.x;
    int warp = tid >> 5, lane = tid & 31;
    int wm = warp >> 2, wn = warp & 3;          // 2 x 4 warp grid -> 64x32 tiles
    int g = lane >> 2, tig = lane & 3;
    int rowBase = blockIdx.x * HBM_;
    int colBase = blockIdx.y * HBN_;

    // copy mapping: thread -> row tid>>1, 16-half segment (tid&1)
    int crow = tid >> 1;
    int cseg = (tid & 1) * 16;
    const __half* Arow = A  + (size_t)(rowBase + crow) * K + cseg;
    const __half* Brow = Bt + (size_t)(colBase + crow) * K + cseg;

    // ldmatrix lane address components
    int la_row = lane & 15;                     // A: row within 16-row tile
    int la_col = (lane >> 4) << 3;              // A: 0 or 8 (k halves)
    int lb_row = (lane & 7) + ((lane & 16) >> 1);  // B: row within 16-n group
    int lb_col = lane & 8;                      // B: 0 or 8 (k halves)

    float acc[4][4][4];
#pragma unroll
    for (int mt = 0; mt < 4; mt++)
#pragma unroll
        for (int nt = 0; nt < 4; nt++)
#pragma unroll
            for (int e = 0; e < 4; e++) acc[mt][nt][e] = 0.f;

    auto load_tiles = [&](int k0, int buf) {
        __half* as = hsm + buf * HSTG;
        __half* bs = as + HAS;
        uint32_t ad = (uint32_t)__cvta_generic_to_shared(as + crow * HLD + cseg);
        uint32_t bd = (uint32_t)__cvta_generic_to_shared(bs + crow * HLD + cseg);
        cpa16(Arow + k0,     ad);
        cpa16(Arow + k0 + 8, ad + 16);
        cpa16(Brow + k0,     bd);
        cpa16(Brow + k0 + 8, bd + 16);
        asm volatile("cp.async.commit_group;" ::: "memory");
    };

    int NK = K / HBK_;
    load_tiles(0, 0);
    load_tiles(HBK_, 1);

    for (int it = 0; it < NK; it++) {
        if (it == NK - 1) asm volatile("cp.async.wait_group 0;" ::: "memory");
        else              asm volatile("cp.async.wait_group 1;" ::: "memory");
        __syncthreads();

        const __half* as = hsm + (it % 3) * HSTG;
        const __half* bs = as + HAS;
        uint32_t abase = (uint32_t)__cvta_generic_to_shared(as);
        uint32_t bbase = (uint32_t)__cvta_generic_to_shared(bs);

#pragma unroll
        for (int ks = 0; ks < 2; ks++) {
            int kb = ks * 16;
            uint32_t af[4][4];
#pragma unroll
            for (int mt = 0; mt < 4; mt++) {
                int r0 = wm * 64 + mt * 16;
                uint32_t addr = abase + ((r0 + la_row) * HLD + kb + la_col) * 2;
                ldsm4(af[mt][0], af[mt][1], af[mt][2], af[mt][3], addr);
            }
            uint32_t bf[4][2];
#pragma unroll
            for (int ntp = 0; ntp < 2; ntp++) {
                int c0 = wn * 32 + ntp * 16;
                uint32_t addr = bbase + ((c0 + lb_row) * HLD + kb + lb_col) * 2;
                ldsm4(bf[2 * ntp][0], bf[2 * ntp][1], bf[2 * ntp + 1][0], bf[2 * ntp + 1][1],
                      addr);
            }
#pragma unroll
            for (int mt = 0; mt < 4; mt++)
#pragma unroll
                for (int nt = 0; nt < 4; nt++) {
                    asm volatile(
                        "mma.sync.aligned.m16n8k16.row.col.f32.f16.f16.f32 "
                        "{%0,%1,%2,%3}, {%4,%5,%6,%7}, {%8,%9}, {%0,%1,%2,%3};"
                        : "+f"(acc[mt][nt][0]), "+f"(acc[mt][nt][1]),
                          "+f"(acc[mt][nt][2]), "+f"(acc[mt][nt][3])
                        : "r"(af[mt][0]), "r"(af[mt][1]), "r"(af[mt][2]), "r"(af[mt][3]),
                          "r"(bf[nt][0]), "r"(bf[nt][1]));
                }
        }
        __syncthreads();
        if (it + 2 < NK) load_tiles((it + 2) * HBK_, (it + 2) % 3);
    }

    // epilogue: (c0,c1)->(row, col,col+1); (c2,c3)->(row+8, ...)
#pragma unroll
    for (int mt = 0; mt < 4; mt++) {
        int row = rowBase + wm * 64 + mt * 16 + g;
#pragma unroll
        for (int nt = 0; nt < 4; nt++) {
            int col = colBase + wn * 32 + nt * 8 + 2 * tig;
            float v0 = acc[mt][nt][0], v1 = acc[mt][nt][1];
            float v2 = acc[mt][nt][2], v3 = acc[mt][nt][3];
            if (EP == EP_BIAS) {
                float* C = (float*)Cv;
                v0 += aux[col]; v1 += aux[col + 1];
                v2 += aux[col]; v3 += aux[col + 1];
                *(float2*)(C + (size_t)row * N + col)       = make_float2(v0, v1);
                *(float2*)(C + (size_t)(row + 8) * N + col) = make_float2(v2, v3);
            } else {  // EP_BIAS_GELU_H: fp16 output
                __half* C = (__half*)Cv;
                v0 = gelu_f(v0 + aux[col]); v1 = gelu_f(v1 + aux[col + 1]);
                v2 = gelu_f(v2 + aux[col]); v3 = gelu_f(v3 + aux[col + 1]);
                *(__half2*)(C + (size_t)row * N + col)       = __floats2half2_rn(v0, v1);
                *(__half2*)(C + (size_t)(row + 8) * N + col) = __floats2half2_rn(v2, v3);
            }
        }
    }
}

// ---------------- per-chunk KV / K-sum states ----------------
__global__ void k_chunkstate() {
    int c = blockIdx.x, b = blockIdx.y;
    int base = b * SEQ + c * TCH;
    __shared__ float Ks[TCH][KD], Vs[TCH][KD];
    for (int i = threadIdx.x; i < TCH * KD; i += 256) {
        int t = i >> 6, d = i & 63;
        Ks[t][d] = g_k[(size_t)(base + t) * KD + d];
        Vs[t][d] = g_v[(size_t)(base + t) * KD + d];
    }
    __syncthreads();
    int sidx = b * NCH + c;
    for (int e = threadIdx.x; e < KD * KD; e += 256) {
        int a = e >> 6, v = e & 63;
        float s = 0.f;
#pragma unroll
        for (int t = 0; t < TCH; t++) s += Ks[t][a] * Vs[t][v];
        g_S[(size_t)sidx * KD * KD + e] = s;
    }
    if (threadIdx.x < KD) {
        float s = 0.f;
#pragma unroll
        for (int t = 0; t < TCH; t++) s += Ks[t][threadIdx.x];
        g_ks[sidx * KD + threadIdx.x] = s;
    }
}

// ---------------- exclusive prefix over chunks ----------------
__global__ void k_prefix() {            // grid (17, BATCH), 256 threads
    int b = blockIdx.y;
    if (blockIdx.x < 16) {
        int i = blockIdx.x * 256 + threadIdx.x;
        float run = 0.f;
        for (int c = 0; c < NCH; c++) {
            size_t off = (size_t)(b * NCH + c) * KD * KD + i;
            g_Sp[off] = run;
            run += g_S[off];
        }
    } else if (threadIdx.x < KD) {
        float run = 0.f;
        for (int c = 0; c < NCH; c++) {
            int off = (b * NCH + c) * KD + threadIdx.x;
            g_ksp[off] = run;
            run += g_ks[off];
        }
    }
}

// ---------------- intra + inter chunk attention ----------------
__global__ __launch_bounds__(256) void k_attn() {
    int c = blockIdx.x, b = blockIdx.y;
    int base = b * SEQ + c * TCH;
    int sidx = b * NCH + c;
    __shared__ float Qs[TCH][KD], Ks[TCH][KD], Vs[TCH][KD];
    __shared__ float Sp[KD][KD];
    __shared__ float sc[TCH][TCH];
    __shared__ float dens[TCH];
    __shared__ float ksp[KD];

    for (int i = threadIdx.x; i < TCH * KD; i += 256) {
        int t = i >> 6, d = i & 63;
        Qs[t][d] = g_q[(size_t)(base + t) * KD + d];
        Ks[t][d] = g_k[(size_t)(base + t) * KD + d];
        Vs[t][d] = g_v[(size_t)(base + t) * KD + d];
    }
    for (int i = threadIdx.x; i < KD * KD; i += 256)
        Sp[i >> 6][i & 63] = g_Sp[(size_t)sidx * KD * KD + i];
    if (threadIdx.x < KD) ksp[threadIdx.x] = g_ksp[sidx * KD + threadIdx.x];
    __syncthreads();

    for (int e = threadIdx.x; e < TCH * TCH; e += 256) {
        int t = e / TCH, s = e % TCH;
        float v = 0.f;
        if (s <= t) {
#pragma unroll
            for (int k = 0; k < KD; k++) v += Qs[t][k] * Ks[s][k];
        }
        sc[t][s] = v;
    }
    __syncthreads();

    if (threadIdx.x < TCH) {
        int t = threadIdx.x;
        float d = 0.f;
        for (int s = 0; s <= t; s++) d += sc[t][s];
#pragma unroll
        for (int k = 0; k < KD; k++) d += Qs[t][k] * ksp[k];
        dens[t] = d + 1e-6f;
    }
    __syncthreads();

    for (int e = threadIdx.x; e < TCH * KD; e += 256) {
        int t = e >> 6, j = e & 63;
        float v = 0.f;
#pragma unroll
        for (int s = 0; s < TCH; s++) v += sc[t][s] * Vs[s][j];
#pragma unroll
        for (int k = 0; k < KD; k++) v += Qs[t][k] * Sp[k][j];
        g_attn[(size_t)(base + t) * KD + j] = v / dens[t];
    }
}

// ---------------- LayerNorm (row of 1024), templated output type ----------------
template <typename OutT>
__global__ void k_ln(const float* __restrict__ in, const float* __restrict__ g,
                     const float* __restrict__ b, OutT* __restrict__ out) {
    int r = blockIdx.x;
    const float* x = in + (size_t)r * DIM;
    __shared__ float red[256];
    int t = threadIdx.x;
    float v[4];
    float s = 0.f;
#pragma unroll
    for (int i = 0; i < 4; i++) { v[i] = x[t + 256 * i]; s += v[i]; }
    red[t] = s;
    __syncthreads();
    for (int o = 128; o > 0; o >>= 1) {
        if (t < o) red[t] += red[t + o];
        __syncthreads();
    }
    float mean = red[0] * (1.f / DIM);
    __syncthreads();
    float q = 0.f;
#pragma unroll
    for (int i = 0; i < 4; i++) { float d = v[i] - mean; q += d * d; }
    red[t] = q;
    __syncthreads();
    for (int o = 128; o > 0; o >>= 1) {
        if (t < o) red[t] += red[t + o];
        __syncthreads();
    }
    float rstd = rsqrtf(red[0] * (1.f / DIM) + 1e-5f);
    OutT* o = out + (size_t)r * DIM;
#pragma unroll
    for (int i = 0; i < 4; i++) {
        int col = t + 256 * i;
        float val = (v[i] - mean) * rstd * g[col] + b[col];
        o[col] = (OutT)val;
    }
}

// ---------------- launch ----------------
extern "C" void kernel_launch(void* const* d_in, const int* in_sizes, int n_in,
                              void* d_out, int out_size) {
    const int*   idx = (const int*)d_in[0];
    const float* tok = (const float*)d_in[1];
    const float* pos = (const float*)d_in[2];
    const float* Wq  = (const float*)d_in[3];
    const float* Wk  = (const float*)d_in[4];
    const float* Wv  = (const float*)d_in[5];
    const float* Wo  = (const float*)d_in[6];
    const float* ng  = (const float*)d_in[7];
    const float* nb  = (const float*)d_in[8];
    const float* og  = (const float*)d_in[9];
    const float* ob  = (const float*)d_in[10];
    const float* W1  = (const float*)d_in[11];
    const float* b1  = (const float*)d_in[12];
    const float* W2  = (const float*)d_in[13];
    const float* b2  = (const float*)d_in[14];
    float* out = (float*)d_out;

    float *px, *py, *pa;
    __half *pxh, *phh, *pw1t, *pw2t;
    cudaGetSymbolAddress((void**)&px,  g_x);
    cudaGetSymbolAddress((void**)&py,  g_y);
    cudaGetSymbolAddress((void**)&pa,  g_attn);
    cudaGetSymbolAddress((void**)&pxh, g_xh);
    cudaGetSymbolAddress((void**)&phh, g_hh);
    cudaGetSymbolAddress((void**)&pw1t, g_w1t);
    cudaGetSymbolAddress((void**)&pw2t, g_w2t);

    cudaFuncSetAttribute(k_hgemm<EP_BIAS>, cudaFuncAttributeMaxDynamicSharedMemorySize, HSMEM_BYTES);
    cudaFuncSetAttribute(k_hgemm<EP_BIAS_GELU_H>, cudaFuncAttributeMaxDynamicSharedMemorySize, HSMEM_BYTES);

    // one-time weight transposes+converts (part of the graph)
    k_transcvt<<<dim3(HID / 32, DIM / 32), dim3(32, 8)>>>(W1, pw1t, DIM, HID);
    k_transcvt<<<dim3(VOCAB / 32, HID / 32), dim3(32, 8)>>>(W2, pw2t, HID, VOCAB);

    k_embed<<<MTOT, 256>>>(idx, tok, pos);

    for (int layer = 0; layer < NH; layer++) {
        const float* wo = Wo + (size_t)layer * KD * DIM;

        k_qkv<<<dim3(1, MTOT / 64, 3), 256>>>(Wq + (size_t)layer * DIM * KD,
                                              Wk + (size_t)layer * DIM * KD,
                                              Wv + (size_t)layer * DIM * KD);
        k_chunkstate<<<dim3(NCH, BATCH), 256>>>();
        k_prefix<<<dim3(17, BATCH), 256>>>();
        k_attn<<<dim3(NCH, BATCH), 256>>>();

        // y = attn @ Wo + x  (residual fused, fp32 SIMT)
        k_sgemm<EP_RESADD><<<dim3(DIM / 128, MTOT / 128), 256>>>(pa, wo, py, MTOT, DIM, KD, px);
        // x = LN(y)
        k_ln<float><<<MTOT, 256>>>(py, ng + layer * DIM, nb + layer * DIM, px);
    }

    // final LN straight to fp16
    k_ln<__half><<<MTOT, 256>>>(px, og, ob, pxh);
    // h = gelu(xn @ W1 + b1)  [fp16 mma, fp16 output]
    k_hgemm<EP_BIAS_GELU_H><<<dim3(MTOT / HBM_, HID / HBN_), 256, HSMEM_BYTES>>>(
        pxh, pw1t, phh, MTOT, HID, DIM, b1);
    // logits = h @ W2 + b2    [fp16 mma, fp32 output]
    k_hgemm<EP_BIAS><<<dim3(MTOT / HBM_, VOCAB / HBN_), 256, HSMEM_BYTES>>>(
        phh, pw2t, out, MTOT, VOCAB, HID, b2);
}

// round 9
// speedup vs baseline: 5.8412x; 1.0282x over previous
#include <cuda_runtime.h>
#include <cuda_fp16.h>
#include <math.h>
#include <stdint.h>

// ---------------- problem constants ----------------
constexpr int BATCH = 2;
constexpr int SEQ   = 2048;
constexpr int MTOT  = BATCH * SEQ;   // 4096 rows
constexpr int DIM   = 1024;
constexpr int KD    = 64;
constexpr int HID   = 4096;
constexpr int VOCAB = 32000;
constexpr int NH    = 2;
constexpr int TCH   = 32;            // chunk length
constexpr int NCH   = SEQ / TCH;     // 64 chunks per batch
constexpr int QKVW  = 256;           // padded packed QKV width (Q|K|V|pad)

// ---------------- device scratch ----------------
__device__ float g_x[MTOT * DIM];
__device__ float g_y[MTOT * DIM];                    // pre-LN residual scratch
__device__ float g_qkv[MTOT * QKVW];                 // fp32 Q|K|V|pad, stride 256
__device__ float g_attn[MTOT * KD];
__device__ float g_S [BATCH * NCH * KD * KD];
__device__ float g_ks[BATCH * NCH * KD];
__device__ __half g_xh [MTOT * DIM];                 // fp16 x (LN output)
__device__ __half g_hh [(size_t)MTOT * HID];         // fp16 hidden
__device__ __half g_w1t[(size_t)HID * DIM];          // W1^T [N,K] fp16
__device__ __half g_w2t[(size_t)VOCAB * HID];        // W2^T [N,K] fp16
__device__ __half g_wqkvt[(size_t)NH * QKVW * DIM];  // packed Wq|Wk|Wv^T fp16; pad rows stay 0 (BSS)

__device__ __forceinline__ float gelu_f(float v) {
    return 0.5f * v * (1.f + erff(v * 0.70710678118654752f));
}

// ---------------- embedding (writes fp32 + fp16) ----------------
__global__ void k_embed(const int* __restrict__ idx,
                        const float* __restrict__ tok,
                        const float* __restrict__ pos) {
    int i = blockIdx.x;
    int l = i & (SEQ - 1);
    int row = idx[i];
    const float4* t = (const float4*)(tok + (size_t)row * DIM);
    const float4* p = (const float4*)(pos + (size_t)l * DIM);
    int d = threadIdx.x;
    float4 a = t[d], b = p[d];
    float4 s = make_float4(a.x + b.x, a.y + b.y, a.z + b.z, a.w + b.w);
    ((float4*)(g_x + (size_t)i * DIM))[d] = s;
    __half* oh = g_xh + (size_t)i * DIM + 4 * d;
    *(__half2*)(oh)     = __floats2half2_rn(s.x, s.y);
    *(__half2*)(oh + 2) = __floats2half2_rn(s.z, s.w);
}

// ---------------- transpose + fp32->fp16 convert: dst[n][k] = src[k][n] ----------------
__global__ void k_transcvt(const float* __restrict__ src, __half* __restrict__ dst,
                           int K, int N) {
    __shared__ float t[32][33];
    int k0 = blockIdx.y * 32, n0 = blockIdx.x * 32;
    int tx = threadIdx.x, ty = threadIdx.y;          // 32 x 8
#pragma unroll
    for (int i = 0; i < 4; i++)
        t[ty + 8 * i][tx] = src[(size_t)(k0 + ty + 8 * i) * N + n0 + tx];
    __syncthreads();
#pragma unroll
    for (int i = 0; i < 4; i++)
        dst[(size_t)(n0 + ty + 8 * i) * K + k0 + tx] = __float2half(t[tx][ty + 8 * i]);
}

// ---------------- SIMT SGEMM (Wo with residual, fp32) ----------------
enum { EP_BIAS = 2, EP_BIAS_GELU_H = 3, EP_RESADD = 4, EP_QKV = 5 };

template <int EP>
__global__ __launch_bounds__(256)
void k_sgemm(const float* __restrict__ A, const float* __restrict__ Bm,
             float* __restrict__ C, int M, int N, int K,
             const float* __restrict__ aux) {
    constexpr int BM = 128, BN = 128, BK = 8, TM = 8, TN = 8;
    __shared__ float As[BK][BM];
    __shared__ float Bs[BK][BN];

    int tid = threadIdx.x;
    int tr = (tid >> 4) * TM;
    int tc = (tid & 15) * TN;
    int rowBase = blockIdx.y * BM;
    int colBase = blockIdx.x * BN;

    float acc[TM][TN];
#pragma unroll
    for (int i = 0; i < TM; i++)
#pragma unroll
        for (int j = 0; j < TN; j++) acc[i][j] = 0.f;

    int arow = tid >> 1;
    int acol = (tid & 1) * 4;
    int brl  = tid >> 5;
    int bcl  = (tid & 31) * 4;
    const float* Aptr = A + (size_t)(rowBase + arow) * K + acol;
    int gc = colBase + bcl;

    for (int k0 = 0; k0 < K; k0 += BK) {
        float4 av = *(const float4*)(Aptr + k0);
        As[acol + 0][arow] = av.x;
        As[acol + 1][arow] = av.y;
        As[acol + 2][arow] = av.z;
        As[acol + 3][arow] = av.w;
        *(float4*)&Bs[brl][bcl] = *(const float4*)(Bm + (size_t)(k0 + brl) * N + gc);
        __syncthreads();
#pragma unroll
        for (int kk = 0; kk < BK; kk++) {
            float a[TM], b[TN];
#pragma unroll
            for (int i = 0; i < TM; i++) a[i] = As[kk][tr + i];
#pragma unroll
            for (int j = 0; j < TN; j++) b[j] = Bs[kk][tc + j];
#pragma unroll
            for (int i = 0; i < TM; i++)
#pragma unroll
                for (int j = 0; j < TN; j++) acc[i][j] += a[i] * b[j];
        }
        __syncthreads();
    }

#pragma unroll
    for (int i = 0; i < TM; i++) {
        int r = rowBase + tr + i;
#pragma unroll
        for (int j = 0; j < TN; j++) {
            int c = colBase + tc + j;
            float v = acc[i][j];
            if (EP == EP_BIAS) v += aux[c];
            else if (EP == EP_RESADD) v += aux[(size_t)r * N + c];
            C[(size_t)r * N + c] = v;
        }
    }
}

// ============ fp16 tensor-core GEMM: C = A[M,K] @ Bt[N,K]^T (+epilogue) ============
// 128x128x32 tiles, 8 warps x (64x32), mma.sync m16n8k16, fp32 accum,
// ldmatrix.x4 fragment loads (conflict-free, 80B row stride), 3-stage cp.async.
constexpr int HBM_ = 128, HBN_ = 128, HBK_ = 32;
constexpr int HLD  = 40;
constexpr int HAS  = HBM_ * HLD;
constexpr int HBS  = HBN_ * HLD;
constexpr int HSTG = HAS + HBS;
constexpr int HSMEM_BYTES = 3 * HSTG * 2;      // 61440

__device__ __forceinline__ void cpa16(const __half* src, uint32_t smem_dst) {
    asm volatile("cp.async.cg.shared.global [%0], [%1], 16;" :: "r"(smem_dst), "l"(src));
}
__device__ __forceinline__ void ldsm4(uint32_t& r0, uint32_t& r1, uint32_t& r2, uint32_t& r3,
                                      uint32_t addr) {
    asm volatile("ldmatrix.sync.aligned.m8n8.x4.shared.b16 {%0,%1,%2,%3}, [%4];"
                 : "=r"(r0), "=r"(r1), "=r"(r2), "=r"(r3) : "r"(addr));
}

template <int EP>
__global__ __launch_bounds__(256)
void k_hgemm(const __half* __restrict__ A, const __half* __restrict__ Bt,
             void* __restrict__ Cv, int M, int N, int K,
             const float* __restrict__ aux) {
    extern __shared__ __half hsm[];

    int tid  = threadIdx.x;
    int warp = tid >> 5, lane = tid & 31;
    int wm = warp >> 2, wn = warp & 3;
    int g = lane >> 2, tig = lane & 3;
    int rowBase = blockIdx.x * HBM_;
    int colBase = blockIdx.y * HBN_;

    int crow = tid >> 1;
    int cseg = (tid & 1) * 16;
    const __half* Arow = A  + (size_t)(rowBase + crow) * K + cseg;
    const __half* Brow = Bt + (size_t)(colBase + crow) * K + cseg;

    int la_row = lane & 15;
    int la_col = (lane >> 4) << 3;
    int lb_row = (lane & 7) + ((lane & 16) >> 1);
    int lb_col = lane & 8;

    float acc[4][4][4];
#pragma unroll
    for (int mt = 0; mt < 4; mt++)
#pragma unroll
        for (int nt = 0; nt < 4; nt++)
#pragma unroll
            for (int e = 0; e < 4; e++) acc[mt][nt][e] = 0.f;

    auto load_tiles = [&](int k0, int buf) {
        __half* as = hsm + buf * HSTG;
        __half* bs = as + HAS;
        uint32_t ad = (uint32_t)__cvta_generic_to_shared(as + crow * HLD + cseg);
        uint32_t bd = (uint32_t)__cvta_generic_to_shared(bs + crow * HLD + cseg);
        cpa16(Arow + k0,     ad);
        cpa16(Arow + k0 + 8, ad + 16);
        cpa16(Brow + k0,     bd);
        cpa16(Brow + k0 + 8, bd + 16);
        asm volatile("cp.async.commit_group;" ::: "memory");
    };

    int NK = K / HBK_;
    load_tiles(0, 0);
    load_tiles(HBK_, 1);

    for (int it = 0; it < NK; it++) {
        if (it == NK - 1) asm volatile("cp.async.wait_group 0;" ::: "memory");
        else              asm volatile("cp.async.wait_group 1;" ::: "memory");
        __syncthreads();

        const __half* as = hsm + (it % 3) * HSTG;
        const __half* bs = as + HAS;
        uint32_t abase = (uint32_t)__cvta_generic_to_shared(as);
        uint32_t bbase = (uint32_t)__cvta_generic_to_shared(bs);

#pragma unroll
        for (int ks = 0; ks < 2; ks++) {
            int kb = ks * 16;
            uint32_t af[4][4];
#pragma unroll
            for (int mt = 0; mt < 4; mt++) {
                int r0 = wm * 64 + mt * 16;
                uint32_t addr = abase + ((r0 + la_row) * HLD + kb + la_col) * 2;
                ldsm4(af[mt][0], af[mt][1], af[mt][2], af[mt][3], addr);
            }
            uint32_t bf[4][2];
#pragma unroll
            for (int ntp = 0; ntp < 2; ntp++) {
                int c0 = wn * 32 + ntp * 16;
                uint32_t addr = bbase + ((c0 + lb_row) * HLD + kb + lb_col) * 2;
                ldsm4(bf[2 * ntp][0], bf[2 * ntp][1], bf[2 * ntp + 1][0], bf[2 * ntp + 1][1],
                      addr);
            }
#pragma unroll
            for (int mt = 0; mt < 4; mt++)
#pragma unroll
                for (int nt = 0; nt < 4; nt++) {
                    asm volatile(
                        "mma.sync.aligned.m16n8k16.row.col.f32.f16.f16.f32 "
                        "{%0,%1,%2,%3}, {%4,%5,%6,%7}, {%8,%9}, {%0,%1,%2,%3};"
                        : "+f"(acc[mt][nt][0]), "+f"(acc[mt][nt][1]),
                          "+f"(acc[mt][nt][2]), "+f"(acc[mt][nt][3])
                        : "r"(af[mt][0]), "r"(af[mt][1]), "r"(af[mt][2]), "r"(af[mt][3]),
                          "r"(bf[nt][0]), "r"(bf[nt][1]));
                }
        }
        __syncthreads();
        if (it + 2 < NK) load_tiles((it + 2) * HBK_, (it + 2) % 3);
    }

#pragma unroll
    for (int mt = 0; mt < 4; mt++) {
        int row = rowBase + wm * 64 + mt * 16 + g;
#pragma unroll
        for (int nt = 0; nt < 4; nt++) {
            int col = colBase + wn * 32 + nt * 8 + 2 * tig;
            float v0 = acc[mt][nt][0], v1 = acc[mt][nt][1];
            float v2 = acc[mt][nt][2], v3 = acc[mt][nt][3];
            if (EP == EP_BIAS) {
                float* C = (float*)Cv;
                v0 += aux[col]; v1 += aux[col + 1];
                v2 += aux[col]; v3 += aux[col + 1];
                *(float2*)(C + (size_t)row * N + col)       = make_float2(v0, v1);
                *(float2*)(C + (size_t)(row + 8) * N + col) = make_float2(v2, v3);
            } else if (EP == EP_BIAS_GELU_H) {
                __half* C = (__half*)Cv;
                v0 = gelu_f(v0 + aux[col]); v1 = gelu_f(v1 + aux[col + 1]);
                v2 = gelu_f(v2 + aux[col]); v3 = gelu_f(v3 + aux[col + 1]);
                *(__half2*)(C + (size_t)row * N + col)       = __floats2half2_rn(v0, v1);
                *(__half2*)(C + (size_t)(row + 8) * N + col) = __floats2half2_rn(v2, v3);
            } else {  // EP_QKV: elu+1 on cols<128 (Q,K), identity on V/pad, fp32 out
                float* C = (float*)Cv;
                if (col < 128) {
                    v0 = (v0 > 0.f) ? (v0 + 1.f) : __expf(v0);
                    v1 = (v1 > 0.f) ? (v1 + 1.f) : __expf(v1);
                    v2 = (v2 > 0.f) ? (v2 + 1.f) : __expf(v2);
                    v3 = (v3 > 0.f) ? (v3 + 1.f) : __expf(v3);
                }
                *(float2*)(C + (size_t)row * N + col)       = make_float2(v0, v1);
                *(float2*)(C + (size_t)(row + 8) * N + col) = make_float2(v2, v3);
            }
        }
    }
}

// ---------------- per-chunk KV / K-sum states (reads packed g_qkv) ----------------
__global__ void k_chunkstate() {
    int c = blockIdx.x, b = blockIdx.y;
    int base = b * SEQ + c * TCH;
    __shared__ float Ks[TCH][KD], Vs[TCH][KD];
    for (int i = threadIdx.x; i < TCH * KD; i += 256) {
        int t = i >> 6, d = i & 63;
        Ks[t][d] = g_qkv[(size_t)(base + t) * QKVW + 64 + d];
        Vs[t][d] = g_qkv[(size_t)(base + t) * QKVW + 128 + d];
    }
    __syncthreads();
    int sidx = b * NCH + c;
    for (int e = threadIdx.x; e < KD * KD; e += 256) {
        int a = e >> 6, v = e & 63;
        float s = 0.f;
#pragma unroll
        for (int t = 0; t < TCH; t++) s += Ks[t][a] * Vs[t][v];
        g_S[(size_t)sidx * KD * KD + e] = s;
    }
    if (threadIdx.x < KD) {
        float s = 0.f;
#pragma unroll
        for (int t = 0; t < TCH; t++) s += Ks[t][threadIdx.x];
        g_ks[sidx * KD + threadIdx.x] = s;
    }
}

// ---------------- intra + inter chunk attention (own prefix over g_S) ----------------
__global__ __launch_bounds__(256) void k_attn() {
    int c = blockIdx.x, b = blockIdx.y;
    int base = b * SEQ + c * TCH;
    __shared__ float Qs[TCH][KD], Ks[TCH][KD], Vs[TCH][KD];
    __shared__ float Sp[KD][KD];
    __shared__ float sc[TCH][TCH];
    __shared__ float dens[TCH];
    __shared__ float ksp[KD];

    for (int i = threadIdx.x; i < TCH * KD; i += 256) {
        int t = i >> 6, d = i & 63;
        Qs[t][d] = g_qkv[(size_t)(base + t) * QKVW + d];
        Ks[t][d] = g_qkv[(size_t)(base + t) * QKVW + 64 + d];
        Vs[t][d] = g_qkv[(size_t)(base + t) * QKVW + 128 + d];
    }
    // exclusive prefix of chunk states (L2-resident g_S)
    for (int i = threadIdx.x; i < KD * KD; i += 256) {
        float run = 0.f;
        for (int cc = 0; cc < c; cc++)
            run += g_S[(size_t)(b * NCH + cc) * KD * KD + i];
        Sp[i >> 6][i & 63] = run;
    }
    if (threadIdx.x < KD) {
        float run = 0.f;
        for (int cc = 0; cc < c; cc++)
            run += g_ks[(b * NCH + cc) * KD + threadIdx.x];
        ksp[threadIdx.x] = run;
    }
    __syncthreads();

    for (int e = threadIdx.x; e < TCH * TCH; e += 256) {
        int t = e / TCH, s = e % TCH;
        float v = 0.f;
        if (s <= t) {
#pragma unroll
            for (int k = 0; k < KD; k++) v += Qs[t][k] * Ks[s][k];
        }
        sc[t][s] = v;
    }
    __syncthreads();

    if (threadIdx.x < TCH) {
        int t = threadIdx.x;
        float d = 0.f;
        for (int s = 0; s <= t; s++) d += sc[t][s];
#pragma unroll
        for (int k = 0; k < KD; k++) d += Qs[t][k] * ksp[k];
        dens[t] = d + 1e-6f;
    }
    __syncthreads();

    for (int e = threadIdx.x; e < TCH * KD; e += 256) {
        int t = e >> 6, j = e & 63;
        float v = 0.f;
#pragma unroll
        for (int s = 0; s < TCH; s++) v += sc[t][s] * Vs[s][j];
#pragma unroll
        for (int k = 0; k < KD; k++) v += Qs[t][k] * Sp[k][j];
        g_attn[(size_t)(base + t) * KD + j] = v / dens[t];
    }
}

// ---------------- one-pass LayerNorm: fp32 out + optional fp16 out ----------------
__global__ void k_ln2(const float* __restrict__ in, const float* __restrict__ g,
                      const float* __restrict__ b, float* __restrict__ outf,
                      __half* __restrict__ outh) {
    int r = blockIdx.x;
    int t = threadIdx.x;                      // 256 threads, 4 elems each
    float4 v = ((const float4*)(in + (size_t)r * DIM))[t];
    float s = v.x + v.y + v.z + v.w;
    float q = v.x * v.x + v.y * v.y + v.z * v.z + v.w * v.w;
#pragma unroll
    for (int o = 16; o > 0; o >>= 1) {
        s += __shfl_xor_sync(0xFFFFFFFFu, s, o);
        q += __shfl_xor_sync(0xFFFFFFFFu, q, o);
    }
    __shared__ float ss[8], qq[8];
    if ((t & 31) == 0) { ss[t >> 5] = s; qq[t >> 5] = q; }
    __syncthreads();
    if (t < 32) {
        float s2 = (t < 8) ? ss[t] : 0.f;
        float q2 = (t < 8) ? qq[t] : 0.f;
#pragma unroll
        for (int o = 4; o > 0; o >>= 1) {
            s2 += __shfl_xor_sync(0xFFFFFFFFu, s2, o);
            q2 += __shfl_xor_sync(0xFFFFFFFFu, q2, o);
        }
        if (t == 0) { ss[0] = s2; qq[0] = q2; }
    }
    __syncthreads();
    float mean = ss[0] * (1.f / DIM);
    float var  = qq[0] * (1.f / DIM) - mean * mean;
    float rstd = rsqrtf(var + 1e-5f);

    float4 gv = ((const float4*)g)[t];
    float4 bv = ((const float4*)b)[t];
    float4 o;
    o.x = (v.x - mean) * rstd * gv.x + bv.x;
    o.y = (v.y - mean) * rstd * gv.y + bv.y;
    o.z = (v.z - mean) * rstd * gv.z + bv.z;
    o.w = (v.w - mean) * rstd * gv.w + bv.w;
    ((float4*)(outf + (size_t)r * DIM))[t] = o;
    if (outh) {
        __half* oh = outh + (size_t)r * DIM + 4 * t;
        *(__half2*)(oh)     = __floats2half2_rn(o.x, o.y);
        *(__half2*)(oh + 2) = __floats2half2_rn(o.z, o.w);
    }
}

// ---------------- launch ----------------
extern "C" void kernel_launch(void* const* d_in, const int* in_sizes, int n_in,
                              void* d_out, int out_size) {
    const int*   idx = (const int*)d_in[0];
    const float* tok = (const float*)d_in[1];
    const float* pos = (const float*)d_in[2];
    const float* Wq  = (const float*)d_in[3];
    const float* Wk  = (const float*)d_in[4];
    const float* Wv  = (const float*)d_in[5];
    const float* Wo  = (const float*)d_in[6];
    const float* ng  = (const float*)d_in[7];
    const float* nb  = (const float*)d_in[8];
    const float* og  = (const float*)d_in[9];
    const float* ob  = (const float*)d_in[10];
    const float* W1  = (const float*)d_in[11];
    const float* b1  = (const float*)d_in[12];
    const float* W2  = (const float*)d_in[13];
    const float* b2  = (const float*)d_in[14];
    float* out = (float*)d_out;

    float *px, *py, *pa, *pqkv;
    __half *pxh, *phh, *pw1t, *pw2t, *pwqkvt;
    cudaGetSymbolAddress((void**)&px,  g_x);
    cudaGetSymbolAddress((void**)&py,  g_y);
    cudaGetSymbolAddress((void**)&pa,  g_attn);
    cudaGetSymbolAddress((void**)&pqkv, g_qkv);
    cudaGetSymbolAddress((void**)&pxh, g_xh);
    cudaGetSymbolAddress((void**)&phh, g_hh);
    cudaGetSymbolAddress((void**)&pw1t, g_w1t);
    cudaGetSymbolAddress((void**)&pw2t, g_w2t);
    cudaGetSymbolAddress((void**)&pwqkvt, g_wqkvt);

    cudaFuncSetAttribute(k_hgemm<EP_BIAS>, cudaFuncAttributeMaxDynamicSharedMemorySize, HSMEM_BYTES);
    cudaFuncSetAttribute(k_hgemm<EP_BIAS_GELU_H>, cudaFuncAttributeMaxDynamicSharedMemorySize, HSMEM_BYTES);
    cudaFuncSetAttribute(k_hgemm<EP_QKV>, cudaFuncAttributeMaxDynamicSharedMemorySize, HSMEM_BYTES);

    // one-time weight transposes+converts (graph nodes)
    k_transcvt<<<dim3(HID / 32, DIM / 32), dim3(32, 8)>>>(W1, pw1t, DIM, HID);
    k_transcvt<<<dim3(VOCAB / 32, HID / 32), dim3(32, 8)>>>(W2, pw2t, HID, VOCAB);
    for (int l = 0; l < NH; l++) {
        k_transcvt<<<dim3(KD / 32, DIM / 32), dim3(32, 8)>>>(
            Wq + (size_t)l * DIM * KD, pwqkvt + ((size_t)l * QKVW + 0)   * DIM, DIM, KD);
        k_transcvt<<<dim3(KD / 32, DIM / 32), dim3(32, 8)>>>(
            Wk + (size_t)l * DIM * KD, pwqkvt + ((size_t)l * QKVW + 64)  * DIM, DIM, KD);
        k_transcvt<<<dim3(KD / 32, DIM / 32), dim3(32, 8)>>>(
            Wv + (size_t)l * DIM * KD, pwqkvt + ((size_t)l * QKVW + 128) * DIM, DIM, KD);
    }

    k_embed<<<MTOT, 256>>>(idx, tok, pos);

    for (int layer = 0; layer < NH; layer++) {
        const float* wo = Wo + (size_t)layer * KD * DIM;

        // QKV = x(fp16) @ packed W^T  [fp16 mma; elu+1 fused for Q,K]
        k_hgemm<EP_QKV><<<dim3(MTOT / HBM_, QKVW / HBN_), 256, HSMEM_BYTES>>>(
            pxh, pwqkvt + (size_t)layer * QKVW * DIM, pqkv, MTOT, QKVW, DIM, nullptr);
        k_chunkstate<<<dim3(NCH, BATCH), 256>>>();
        k_attn<<<dim3(NCH, BATCH), 256>>>();

        // y = attn @ Wo + x  (residual fused, fp32 SIMT)
        k_sgemm<EP_RESADD><<<dim3(DIM / 128, MTOT / 128), 256>>>(pa, wo, py, MTOT, DIM, KD, px);
        // x = LN(y), fp32 + fp16
        k_ln2<<<MTOT, 256>>>(py, ng + layer * DIM, nb + layer * DIM, px, pxh);
    }

    // final LN (fp16 consumed by GEMM1; fp32 to scratch)
    k_ln2<<<MTOT, 256>>>(px, og, ob, py, pxh);
    // h = gelu(xn @ W1 + b1)  [fp16 mma, fp16 output]
    k_hgemm<EP_BIAS_GELU_H><<<dim3(MTOT / HBM_, HID / HBN_), 256, HSMEM_BYTES>>>(
        pxh, pw1t, phh, MTOT, HID, DIM, b1);
    // logits = h @ W2 + b2    [fp16 mma, fp32 output]
    k_hgemm<EP_BIAS><<<dim3(MTOT / HBM_, VOCAB / HBN_), 256, HSMEM_BYTES>>>(
        phh, pw2t, out, MTOT, VOCAB, HID, b2);
}

// round 11
// speedup vs baseline: 5.9222x; 1.0139x over previous
#include <cuda_runtime.h>
#include <cuda_fp16.h>
#include <math.h>
#include <stdint.h>

// ---------------- problem constants ----------------
constexpr int BATCH = 2;
constexpr int SEQ   = 2048;
constexpr int MTOT  = BATCH * SEQ;   // 4096 rows
constexpr int DIM   = 1024;
constexpr int KD    = 64;
constexpr int HID   = 4096;
constexpr int VOCAB = 32000;
constexpr int NH    = 2;
constexpr int TCH   = 32;            // chunk length
constexpr int NCH   = SEQ / TCH;     // 64 chunks per batch
constexpr int QKVW  = 256;           // padded packed QKV width (Q|K|V|pad)

// ---------------- device scratch ----------------
__device__ float g_x[MTOT * DIM];
__device__ float g_y[MTOT * DIM];                    // pre-LN residual scratch
__device__ float g_qkv[MTOT * QKVW];                 // fp32 Q|K|V|pad, stride 256
__device__ float g_S [BATCH * NCH * KD * KD];
__device__ float g_Sp[BATCH * NCH * KD * KD];
__device__ float g_ks [BATCH * NCH * KD];
__device__ float g_ksp[BATCH * NCH * KD];
__device__ __half g_attnh[MTOT * KD];                // fp16 attn output
__device__ __half g_xh [MTOT * DIM];                 // fp16 x (LN output)
__device__ __half g_hh [(size_t)MTOT * HID];         // fp16 hidden
__device__ __half g_w1t[(size_t)HID * DIM];          // W1^T [N,K] fp16
__device__ __half g_w2t[(size_t)VOCAB * HID];        // W2^T [N,K] fp16
__device__ __half g_wot[(size_t)NH * DIM * KD];      // Wo^T [DIM,KD] fp16 per layer
__device__ __half g_wqkvt[(size_t)NH * QKVW * DIM];  // packed Wq|Wk|Wv^T fp16; pad rows stay 0

__device__ __forceinline__ float gelu_f(float v) {
    return 0.5f * v * (1.f + erff(v * 0.70710678118654752f));
}

// ---------------- embedding (writes fp32 + fp16) ----------------
__global__ void k_embed(const int* __restrict__ idx,
                        const float* __restrict__ tok,
                        const float* __restrict__ pos) {
    int i = blockIdx.x;
    int l = i & (SEQ - 1);
    int row = idx[i];
    const float4* t = (const float4*)(tok + (size_t)row * DIM);
    const float4* p = (const float4*)(pos + (size_t)l * DIM);
    int d = threadIdx.x;
    float4 a = t[d], b = p[d];
    float4 s = make_float4(a.x + b.x, a.y + b.y, a.z + b.z, a.w + b.w);
    ((float4*)(g_x + (size_t)i * DIM))[d] = s;
    __half* oh = g_xh + (size_t)i * DIM + 4 * d;
    *(__half2*)(oh)     = __floats2half2_rn(s.x, s.y);
    *(__half2*)(oh + 2) = __floats2half2_rn(s.z, s.w);
}

// ---------------- transpose + fp32->fp16 convert: dst[n][k] = src[k][n] ----------------
__global__ void k_transcvt(const float* __restrict__ src, __half* __restrict__ dst,
                           int K, int N) {
    __shared__ float t[32][33];
    int k0 = blockIdx.y * 32, n0 = blockIdx.x * 32;
    int tx = threadIdx.x, ty = threadIdx.y;          // 32 x 8
#pragma unroll
    for (int i = 0; i < 4; i++)
        t[ty + 8 * i][tx] = src[(size_t)(k0 + ty + 8 * i) * N + n0 + tx];
    __syncthreads();
#pragma unroll
    for (int i = 0; i < 4; i++)
        dst[(size_t)(n0 + ty + 8 * i) * K + k0 + tx] = __float2half(t[tx][ty + 8 * i]);
}

// ============ fp16 tensor-core GEMM: C = A[M,K] @ Bt[N,K]^T (+epilogue) ============
// 128x128x32 tiles, 8 warps x (64x32), mma.sync m16n8k16, fp32 accum,
// ldmatrix.x4 fragment loads (conflict-free, 80B row stride), 3-stage cp.async.
enum { EP_BIAS = 2, EP_BIAS_GELU_H = 3, EP_RESADD = 4, EP_QKV = 5 };

constexpr int HBM_ = 128, HBN_ = 128, HBK_ = 32;
constexpr int HLD  = 40;
constexpr int HAS  = HBM_ * HLD;
constexpr int HBS  = HBN_ * HLD;
constexpr int HSTG = HAS + HBS;
constexpr int HSMEM_BYTES = 3 * HSTG * 2;      // 61440

__device__ __forceinline__ void cpa16(const __half* src, uint32_t smem_dst) {
    asm volatile("cp.async.cg.shared.global [%0], [%1], 16;" :: "r"(smem_dst), "l"(src));
}
__device__ __forceinline__ void ldsm4(uint32_t& r0, uint32_t& r1, uint32_t& r2, uint32_t& r3,
                                      uint32_t addr) {
    asm volatile("ldmatrix.sync.aligned.m8n8.x4.shared.b16 {%0,%1,%2,%3}, [%4];"
                 : "=r"(r0), "=r"(r1), "=r"(r2), "=r"(r3) : "r"(addr));
}

template <int EP>
__global__ __launch_bounds__(256)
void k_hgemm(const __half* __restrict__ A, const __half* __restrict__ Bt,
             void* __restrict__ Cv, int M, int N, int K,
             const float* __restrict__ aux) {
    extern __shared__ __half hsm[];

    int tid  = threadIdx.x;
    int warp = tid >> 5, lane = tid & 31;
    int wm = warp >> 2, wn = warp & 3;
    int g = lane >> 2, tig = lane & 3;
    int rowBase = blockIdx.x * HBM_;
    int colBase = blockIdx.y * HBN_;

    int crow = tid >> 1;
    int cseg = (tid & 1) * 16;
    const __half* Arow = A  + (size_t)(rowBase + crow) * K + cseg;
    const __half* Brow = Bt + (size_t)(colBase + crow) * K + cseg;

    int la_row = lane & 15;
    int la_col = (lane >> 4) << 3;
    int lb_row = (lane & 7) + ((lane & 16) >> 1);
    int lb_col = lane & 8;

    float acc[4][4][4];
#pragma unroll
    for (int mt = 0; mt < 4; mt++)
#pragma unroll
        for (int nt = 0; nt < 4; nt++)
#pragma unroll
            for (int e = 0; e < 4; e++) acc[mt][nt][e] = 0.f;

    auto load_tiles = [&](int k0, int buf) {
        __half* as = hsm + buf * HSTG;
        __half* bs = as + HAS;
        uint32_t ad = (uint32_t)__cvta_generic_to_shared(as + crow * HLD + cseg);
        uint32_t bd = (uint32_t)__cvta_generic_to_shared(bs + crow * HLD + cseg);
        cpa16(Arow + k0,     ad);
        cpa16(Arow + k0 + 8, ad + 16);
        cpa16(Brow + k0,     bd);
        cpa16(Brow + k0 + 8, bd + 16);
        asm volatile("cp.async.commit_group;" ::: "memory");
    };

    int NK = K / HBK_;
    load_tiles(0, 0);
    if (NK > 1) load_tiles(HBK_, 1);
    else        asm volatile("cp.async.commit_group;" ::: "memory");

    for (int it = 0; it < NK; it++) {
        if (it == NK - 1) asm volatile("cp.async.wait_group 0;" ::: "memory");
        else              asm volatile("cp.async.wait_group 1;" ::: "memory");
        __syncthreads();

        const __half* as = hsm + (it % 3) * HSTG;
        const __half* bs = as + HAS;
        uint32_t abase = (uint32_t)__cvta_generic_to_shared(as);
        uint32_t bbase = (uint32_t)__cvta_generic_to_shared(bs);

#pragma unroll
        for (int ks = 0; ks < 2; ks++) {
            int kb = ks * 16;
            uint32_t af[4][4];
#pragma unroll
            for (int mt = 0; mt < 4; mt++) {
                int r0 = wm * 64 + mt * 16;
                uint32_t addr = abase + ((r0 + la_row) * HLD + kb + la_col) * 2;
                ldsm4(af[mt][0], af[mt][1], af[mt][2], af[mt][3], addr);
            }
            uint32_t bf[4][2];
#pragma unroll
            for (int ntp = 0; ntp < 2; ntp++) {
                int c0 = wn * 32 + ntp * 16;
                uint32_t addr = bbase + ((c0 + lb_row) * HLD + kb + lb_col) * 2;
                ldsm4(bf[2 * ntp][0], bf[2 * ntp][1], bf[2 * ntp + 1][0], bf[2 * ntp + 1][1],
                      addr);
            }
#pragma unroll
            for (int mt = 0; mt < 4; mt++)
#pragma unroll
                for (int nt = 0; nt < 4; nt++) {
                    asm volatile(
                        "mma.sync.aligned.m16n8k16.row.col.f32.f16.f16.f32 "
                        "{%0,%1,%2,%3}, {%4,%5,%6,%7}, {%8,%9}, {%0,%1,%2,%3};"
                        : "+f"(acc[mt][nt][0]), "+f"(acc[mt][nt][1]),
                          "+f"(acc[mt][nt][2]), "+f"(acc[mt][nt][3])
                        : "r"(af[mt][0]), "r"(af[mt][1]), "r"(af[mt][2]), "r"(af[mt][3]),
                          "r"(bf[nt][0]), "r"(bf[nt][1]));
                }
        }
        __syncthreads();
        if (it + 2 < NK) load_tiles((it + 2) * HBK_, (it + 2) % 3);
    }

#pragma unroll
    for (int mt = 0; mt < 4; mt++) {
        int row = rowBase + wm * 64 + mt * 16 + g;
#pragma unroll
        for (int nt = 0; nt < 4; nt++) {
            int col = colBase + wn * 32 + nt * 8 + 2 * tig;
            float v0 = acc[mt][nt][0], v1 = acc[mt][nt][1];
            float v2 = acc[mt][nt][2], v3 = acc[mt][nt][3];
            if (EP == EP_BIAS) {
                float* C = (float*)Cv;
                v0 += aux[col]; v1 += aux[col + 1];
                v2 += aux[col]; v3 += aux[col + 1];
                *(float2*)(C + (size_t)row * N + col)       = make_float2(v0, v1);
                *(float2*)(C + (size_t)(row + 8) * N + col) = make_float2(v2, v3);
            } else if (EP == EP_BIAS_GELU_H) {
                __half* C = (__half*)Cv;
                v0 = gelu_f(v0 + aux[col]); v1 = gelu_f(v1 + aux[col + 1]);
                v2 = gelu_f(v2 + aux[col]); v3 = gelu_f(v3 + aux[col + 1]);
                *(__half2*)(C + (size_t)row * N + col)       = __floats2half2_rn(v0, v1);
                *(__half2*)(C + (size_t)(row + 8) * N + col) = __floats2half2_rn(v2, v3);
            } else if (EP == EP_RESADD) {      // + fp32 residual, fp32 out
                float* C = (float*)Cv;
                const float* r0p = aux + (size_t)row * N + col;
                const float* r1p = aux + (size_t)(row + 8) * N + col;
                v0 += r0p[0]; v1 += r0p[1];
                v2 += r1p[0]; v3 += r1p[1];
                *(float2*)(C + (size_t)row * N + col)       = make_float2(v0, v1);
                *(float2*)(C + (size_t)(row + 8) * N + col) = make_float2(v2, v3);
            } else {  // EP_QKV: elu+1 on cols<128 (Q,K), identity on V/pad, fp32 out
                float* C = (float*)Cv;
                if (col < 128) {
                    v0 = (v0 > 0.f) ? (v0 + 1.f) : __expf(v0);
                    v1 = (v1 > 0.f) ? (v1 + 1.f) : __expf(v1);
                    v2 = (v2 > 0.f) ? (v2 + 1.f) : __expf(v2);
                    v3 = (v3 > 0.f) ? (v3 + 1.f) : __expf(v3);
                }
                *(float2*)(C + (size_t)row * N + col)       = make_float2(v0, v1);
                *(float2*)(C + (size_t)(row + 8) * N + col) = make_float2(v2, v3);
            }
        }
    }
}

// ---------------- per-chunk KV / K-sum states (reads packed g_qkv) ----------------
__global__ void k_chunkstate() {
    int c = blockIdx.x, b = blockIdx.y;
    int base = b * SEQ + c * TCH;
    __shared__ float Ks[TCH][KD], Vs[TCH][KD];
    for (int i = threadIdx.x; i < TCH * KD; i += 256) {
        int t = i >> 6, d = i & 63;
        Ks[t][d] = g_qkv[(size_t)(base + t) * QKVW + 64 + d];
        Vs[t][d] = g_qkv[(size_t)(base + t) * QKVW + 128 + d];
    }
    __syncthreads();
    int sidx = b * NCH + c;
    for (int e = threadIdx.x; e < KD * KD; e += 256) {
        int a = e >> 6, v = e & 63;
        float s = 0.f;
#pragma unroll
        for (int t = 0; t < TCH; t++) s += Ks[t][a] * Vs[t][v];
        g_S[(size_t)sidx * KD * KD + e] = s;
    }
    if (threadIdx.x < KD) {
        float s = 0.f;
#pragma unroll
        for (int t = 0; t < TCH; t++) s += Ks[t][threadIdx.x];
        g_ks[sidx * KD + threadIdx.x] = s;
    }
}

// ---------------- fast exclusive prefix over chunks ----------------
// grid (129, BATCH), 256 threads. Blocks 0..127: 32 S-elements each via
// smem-staged scan (coalesced loads/stores, 1-warp serial scan in smem).
// Block 128: ks prefix.
__global__ void k_prefix() {
    int b = blockIdx.y;
    if (blockIdx.x < 128) {
        __shared__ float st[NCH][32];
        int i0 = blockIdx.x * 32;
        int t = threadIdx.x;
        int c = t >> 5, il = t & 31;
        for (int cc = c; cc < NCH; cc += 8)
            st[cc][il] = g_S[(size_t)(b * NCH + cc) * (KD * KD) + i0 + il];
        __syncthreads();
        if (t < 32) {
            float run = 0.f;
            for (int cc = 0; cc < NCH; cc++) {
                float v = st[cc][t];
                st[cc][t] = run;
                run += v;
            }
        }
        __syncthreads();
        for (int cc = c; cc < NCH; cc += 8)
            g_Sp[(size_t)(b * NCH + cc) * (KD * KD) + i0 + il] = st[cc][il];
    } else if (threadIdx.x < KD) {
        float run = 0.f;
        for (int c = 0; c < NCH; c++) {
            int off = (b * NCH + c) * KD + threadIdx.x;
            g_ksp[off] = run;
            run += g_ks[off];
        }
    }
}

// ---------------- intra + inter chunk attention (fp16 output) ----------------
__global__ __launch_bounds__(256) void k_attn() {
    int c = blockIdx.x, b = blockIdx.y;
    int base = b * SEQ + c * TCH;
    int sidx = b * NCH + c;
    __shared__ float Qs[TCH][KD], Ks[TCH][KD], Vs[TCH][KD];
    __shared__ float Sp[KD][KD];
    __shared__ float sc[TCH][TCH];
    __shared__ float dens[TCH];
    __shared__ float ksp[KD];

    for (int i = threadIdx.x; i < TCH * KD; i += 256) {
        int t = i >> 6, d = i & 63;
        Qs[t][d] = g_qkv[(size_t)(base + t) * QKVW + d];
        Ks[t][d] = g_qkv[(size_t)(base + t) * QKVW + 64 + d];
        Vs[t][d] = g_qkv[(size_t)(base + t) * QKVW + 128 + d];
    }
    for (int i = threadIdx.x; i < KD * KD; i += 256)
        Sp[i >> 6][i & 63] = g_Sp[(size_t)sidx * KD * KD + i];
    if (threadIdx.x < KD) ksp[threadIdx.x] = g_ksp[sidx * KD + threadIdx.x];
    __syncthreads();

    for (int e = threadIdx.x; e < TCH * TCH; e += 256) {
        int t = e / TCH, s = e % TCH;
        float v = 0.f;
        if (s <= t) {
#pragma unroll
            for (int k = 0; k < KD; k++) v += Qs[t][k] * Ks[s][k];
        }
        sc[t][s] = v;
    }
    __syncthreads();

    if (threadIdx.x < TCH) {
        int t = threadIdx.x;
        float d = 0.f;
        for (int s = 0; s <= t; s++) d += sc[t][s];
#pragma unroll
        for (int k = 0; k < KD; k++) d += Qs[t][k] * ksp[k];
        dens[t] = d + 1e-6f;
    }
    __syncthreads();

    for (int e = threadIdx.x; e < TCH * KD; e += 256) {
        int t = e >> 6, j = e & 63;
        float v = 0.f;
#pragma unroll
        for (int s = 0; s < TCH; s++) v += sc[t][s] * Vs[s][j];
#pragma unroll
        for (int k = 0; k < KD; k++) v += Qs[t][k] * Sp[k][j];
        g_attnh[(size_t)(base + t) * KD + j] = __float2half(v / dens[t]);
    }
}

// ---------------- one-pass LayerNorm: fp32 out + fp16 out ----------------
__global__ void k_ln2(const float* __restrict__ in, const float* __restrict__ g,
                      const float* __restrict__ b, float* __restrict__ outf,
                      __half* __restrict__ outh) {
    int r = blockIdx.x;
    int t = threadIdx.x;                      // 256 threads, 4 elems each
    float4 v = ((const float4*)(in + (size_t)r * DIM))[t];
    float s = v.x + v.y + v.z + v.w;
    float q = v.x * v.x + v.y * v.y + v.z * v.z + v.w * v.w;
#pragma unroll
    for (int o = 16; o > 0; o >>= 1) {
        s += __shfl_xor_sync(0xFFFFFFFFu, s, o);
        q += __shfl_xor_sync(0xFFFFFFFFu, q, o);
    }
    __shared__ float ss[8], qq[8];
    if ((t & 31) == 0) { ss[t >> 5] = s; qq[t >> 5] = q; }
    __syncthreads();
    if (t < 32) {
        float s2 = (t < 8) ? ss[t] : 0.f;
        float q2 = (t < 8) ? qq[t] : 0.f;
#pragma unroll
        for (int o = 4; o > 0; o >>= 1) {
            s2 += __shfl_xor_sync(0xFFFFFFFFu, s2, o);
            q2 += __shfl_xor_sync(0xFFFFFFFFu, q2, o);
        }
        if (t == 0) { ss[0] = s2; qq[0] = q2; }
    }
    __syncthreads();
    float mean = ss[0] * (1.f / DIM);
    float var  = qq[0] * (1.f / DIM) - mean * mean;
    float rstd = rsqrtf(var + 1e-5f);

    float4 gv = ((const float4*)g)[t];
    float4 bv = ((const float4*)b)[t];
    float4 o;
    o.x = (v.x - mean) * rstd * gv.x + bv.x;
    o.y = (v.y - mean) * rstd * gv.y + bv.y;
    o.z = (v.z - mean) * rstd * gv.z + bv.z;
    o.w = (v.w - mean) * rstd * gv.w + bv.w;
    ((float4*)(outf + (size_t)r * DIM))[t] = o;
    __half* oh = outh + (size_t)r * DIM + 4 * t;
    *(__half2*)(oh)     = __floats2half2_rn(o.x, o.y);
    *(__half2*)(oh + 2) = __floats2half2_rn(o.z, o.w);
}

// ---------------- launch ----------------
extern "C" void kernel_launch(void* const* d_in, const int* in_sizes, int n_in,
                              void* d_out, int out_size) {
    const int*   idx = (const int*)d_in[0];
    const float* tok = (const float*)d_in[1];
    const float* pos = (const float*)d_in[2];
    const float* Wq  = (const float*)d_in[3];
    const float* Wk  = (const float*)d_in[4];
    const float* Wv  = (const float*)d_in[5];
    const float* Wo  = (const float*)d_in[6];
    const float* ng  = (const float*)d_in[7];
    const float* nb  = (const float*)d_in[8];
    const float* og  = (const float*)d_in[9];
    const float* ob  = (const float*)d_in[10];
    const float* W1  = (const float*)d_in[11];
    const float* b1  = (const float*)d_in[12];
    const float* W2  = (const float*)d_in[13];
    const float* b2  = (const float*)d_in[14];
    float* out = (float*)d_out;

    float *px, *py, *pqkv;
    __half *pah, *pxh, *phh, *pw1t, *pw2t, *pwot, *pwqkvt;
    cudaGetSymbolAddress((void**)&px,  g_x);
    cudaGetSymbolAddress((void**)&py,  g_y);
    cudaGetSymbolAddress((void**)&pqkv, g_qkv);
    cudaGetSymbolAddress((void**)&pah, g_attnh);
    cudaGetSymbolAddress((void**)&pxh, g_xh);
    cudaGetSymbolAddress((void**)&phh, g_hh);
    cudaGetSymbolAddress((void**)&pw1t, g_w1t);
    cudaGetSymbolAddress((void**)&pw2t, g_w2t);
    cudaGetSymbolAddress((void**)&pwot, g_wot);
    cudaGetSymbolAddress((void**)&pwqkvt, g_wqkvt);

    cudaFuncSetAttribute(k_hgemm<EP_BIAS>, cudaFuncAttributeMaxDynamicSharedMemorySize, HSMEM_BYTES);
    cudaFuncSetAttribute(k_hgemm<EP_BIAS_GELU_H>, cudaFuncAttributeMaxDynamicSharedMemorySize, HSMEM_BYTES);
    cudaFuncSetAttribute(k_hgemm<EP_QKV>, cudaFuncAttributeMaxDynamicSharedMemorySize, HSMEM_BYTES);
    cudaFuncSetAttribute(k_hgemm<EP_RESADD>, cudaFuncAttributeMaxDynamicSharedMemorySize, HSMEM_BYTES);

    // one-time weight transposes+converts (graph nodes)
    k_transcvt<<<dim3(HID / 32, DIM / 32), dim3(32, 8)>>>(W1, pw1t, DIM, HID);
    k_transcvt<<<dim3(VOCAB / 32, HID / 32), dim3(32, 8)>>>(W2, pw2t, HID, VOCAB);
    for (int l = 0; l < NH; l++) {
        k_transcvt<<<dim3(KD / 32, DIM / 32), dim3(32, 8)>>>(
            Wq + (size_t)l * DIM * KD, pwqkvt + ((size_t)l * QKVW + 0)   * DIM, DIM, KD);
        k_transcvt<<<dim3(KD / 32, DIM / 32), dim3(32, 8)>>>(
            Wk + (size_t)l * DIM * KD, pwqkvt + ((size_t)l * QKVW + 64)  * DIM, DIM, KD);
        k_transcvt<<<dim3(KD / 32, DIM / 32), dim3(32, 8)>>>(
            Wv + (size_t)l * DIM * KD, pwqkvt + ((size_t)l * QKVW + 128) * DIM, DIM, KD);
        // Wo [KD, DIM] -> Wo^T [DIM, KD]
        k_transcvt<<<dim3(DIM / 32, KD / 32), dim3(32, 8)>>>(
            Wo + (size_t)l * KD * DIM, pwot + (size_t)l * DIM * KD, KD, DIM);
    }

    k_embed<<<MTOT, 256>>>(idx, tok, pos);

    for (int layer = 0; layer < NH; layer++) {
        // QKV = x(fp16) @ packed W^T  [fp16 mma; elu+1 fused for Q,K]
        k_hgemm<EP_QKV><<<dim3(MTOT / HBM_, QKVW / HBN_), 256, HSMEM_BYTES>>>(
            pxh, pwqkvt + (size_t)layer * QKVW * DIM, pqkv, MTOT, QKVW, DIM, nullptr);
        k_chunkstate<<<dim3(NCH, BATCH), 256>>>();
        k_prefix<<<dim3(129, BATCH), 256>>>();
        k_attn<<<dim3(NCH, BATCH), 256>>>();

        // y = attn @ Wo + x  [fp16 mma, fp32 residual + out]
        k_hgemm<EP_RESADD><<<dim3(MTOT / HBM_, DIM / HBN_), 256, HSMEM_BYTES>>>(
            pah, pwot + (size_t)layer * DIM * KD, py, MTOT, DIM, KD, px);
        // x = LN(y), fp32 + fp16
        k_ln2<<<MTOT, 256>>>(py, ng + layer * DIM, nb + layer * DIM, px, pxh);
    }

    // final LN (fp16 consumed by GEMM1; fp32 to scratch)
    k_ln2<<<MTOT, 256>>>(px, og, ob, py, pxh);
    // h = gelu(xn @ W1 + b1)  [fp16 mma, fp16 output]
    k_hgemm<EP_BIAS_GELU_H><<<dim3(MTOT / HBM_, HID / HBN_), 256, HSMEM_BYTES>>>(
        pxh, pw1t, phh, MTOT, HID, DIM, b1);
    // logits = h @ W2 + b2    [fp16 mma, fp32 output]
    k_hgemm<EP_BIAS><<<dim3(MTOT / HBM_, VOCAB / HBN_), 256, HSMEM_BYTES>>>(
        phh, pw2t, out, MTOT, VOCAB, HID, b2);
}

// round 13
// speedup vs baseline: 5.9293x; 1.0012x over previous
#include <cuda_runtime.h>
#include <cuda_fp16.h>
#include <math.h>
#include <stdint.h>

// ---------------- problem constants ----------------
constexpr int BATCH = 2;
constexpr int SEQ   = 2048;
constexpr int MTOT  = BATCH * SEQ;   // 4096 rows
constexpr int DIM   = 1024;
constexpr int KD    = 64;
constexpr int HID   = 4096;
constexpr int VOCAB = 32000;
constexpr int NH    = 2;
constexpr int TCH   = 32;            // chunk length
constexpr int NCH   = SEQ / TCH;     // 64 chunks per batch
constexpr int QKVW  = 256;           // padded packed QKV width (Q|K|V|pad)

// ---------------- device scratch ----------------
__device__ float g_x[MTOT * DIM];
__device__ float g_y[MTOT * DIM];                    // pre-LN residual scratch
__device__ float g_qkv[MTOT * QKVW];                 // fp32 Q|K|V|pad, stride 256
__device__ float g_S [BATCH * NCH * KD * KD];
__device__ float g_Sp[BATCH * NCH * KD * KD];
__device__ float g_ks [BATCH * NCH * KD];
__device__ float g_ksp[BATCH * NCH * KD];
__device__ __half g_attnh[MTOT * KD];                // fp16 attn output
__device__ __half g_xh [MTOT * DIM];                 // fp16 x (LN output)
__device__ __half g_hh [(size_t)MTOT * HID];         // fp16 hidden
__device__ __half g_w1t[(size_t)HID * DIM];          // W1^T [N,K] fp16
__device__ __half g_w2t[(size_t)VOCAB * HID];        // W2^T [N,K] fp16
__device__ __half g_wot[(size_t)NH * DIM * KD];      // Wo^T [DIM,KD] fp16 per layer
__device__ __half g_wqkvt[(size_t)NH * QKVW * DIM];  // packed Wq|Wk|Wv^T fp16; pad rows stay 0

__device__ __forceinline__ float gelu_f(float v) {
    return 0.5f * v * (1.f + erff(v * 0.70710678118654752f));
}

// ---------------- embedding (writes fp32 + fp16) ----------------
__global__ void k_embed(const int* __restrict__ idx,
                        const float* __restrict__ tok,
                        const float* __restrict__ pos) {
    int i = blockIdx.x;
    int l = i & (SEQ - 1);
    int row = idx[i];
    const float4* t = (const float4*)(tok + (size_t)row * DIM);
    const float4* p = (const float4*)(pos + (size_t)l * DIM);
    int d = threadIdx.x;
    float4 a = t[d], b = p[d];
    float4 s = make_float4(a.x + b.x, a.y + b.y, a.z + b.z, a.w + b.w);
    ((float4*)(g_x + (size_t)i * DIM))[d] = s;
    __half* oh = g_xh + (size_t)i * DIM + 4 * d;
    *(__half2*)(oh)     = __floats2half2_rn(s.x, s.y);
    *(__half2*)(oh + 2) = __floats2half2_rn(s.z, s.w);
}

// ---------------- transpose + fp32->fp16 convert: dst[n][k] = src[k][n] ----------------
__global__ void k_transcvt(const float* __restrict__ src, __half* __restrict__ dst,
                           int K, int N) {
    __shared__ float t[32][33];
    int k0 = blockIdx.y * 32, n0 = blockIdx.x * 32;
    int tx = threadIdx.x, ty = threadIdx.y;          // 32 x 8
#pragma unroll
    for (int i = 0; i < 4; i++)
        t[ty + 8 * i][tx] = src[(size_t)(k0 + ty + 8 * i) * N + n0 + tx];
    __syncthreads();
#pragma unroll
    for (int i = 0; i < 4; i++)
        dst[(size_t)(n0 + ty + 8 * i) * K + k0 + tx] = __float2half(t[tx][ty + 8 * i]);
}

// ---------------- batched small weight transposes (Wq/Wk/Wv/Wo x NH layers) ----------------
// grid (64, 1, NH*4): z = layer*4 + which (0=Wq,1=Wk,2=Wv,3=Wo)
__global__ void k_transcvt_small(const float* __restrict__ Wq, const float* __restrict__ Wk,
                                 const float* __restrict__ Wv, const float* __restrict__ Wo) {
    __shared__ float t[32][33];
    int z = blockIdx.z;
    int l = z >> 2, w = z & 3;
    const float* src;
    __half* dst;
    int K, N;
    if (w < 3) {
        src = (w == 0 ? Wq : w == 1 ? Wk : Wv) + (size_t)l * DIM * KD;
        dst = g_wqkvt + ((size_t)l * QKVW + 64 * w) * DIM;
        K = DIM; N = KD;
    } else {
        src = Wo + (size_t)l * KD * DIM;
        dst = g_wot + (size_t)l * DIM * KD;
        K = KD; N = DIM;
    }
    int nbx = N / 32;
    int bx = blockIdx.x % nbx, by = blockIdx.x / nbx;
    int k0 = by * 32, n0 = bx * 32;
    int tx = threadIdx.x, ty = threadIdx.y;          // 32 x 8
#pragma unroll
    for (int i = 0; i < 4; i++)
        t[ty + 8 * i][tx] = src[(size_t)(k0 + ty + 8 * i) * N + n0 + tx];
    __syncthreads();
#pragma unroll
    for (int i = 0; i < 4; i++)
        dst[(size_t)(n0 + ty + 8 * i) * K + k0 + tx] = __float2half(t[tx][ty + 8 * i]);
}

// ============ fp16 tensor-core GEMM: C = A[M,K] @ Bt[N,K]^T (+epilogue) ============
// 128x128x32 tiles, 8 warps x (64x32), mma.sync m16n8k16, fp32 accum,
// ldmatrix.x4 fragment loads (conflict-free, 80B row stride), 3-stage cp.async.
// EP_BIAS output uses streaming stores (512MB of logits never re-read).
enum { EP_BIAS = 2, EP_BIAS_GELU_H = 3, EP_RESADD = 4, EP_QKV = 5 };

constexpr int HBM_ = 128, HBN_ = 128, HBK_ = 32;
constexpr int HLD  = 40;
constexpr int HAS  = HBM_ * HLD;
constexpr int HBS  = HBN_ * HLD;
constexpr int HSTG = HAS + HBS;
constexpr int HSMEM_BYTES = 3 * HSTG * 2;      // 61440

__device__ __forceinline__ void cpa16(const __half* src, uint32_t smem_dst) {
    asm volatile("cp.async.cg.shared.global [%0], [%1], 16;" :: "r"(smem_dst), "l"(src));
}
__device__ __forceinline__ void ldsm4(uint32_t& r0, uint32_t& r1, uint32_t& r2, uint32_t& r3,
                                      uint32_t addr) {
    asm volatile("ldmatrix.sync.aligned.m8n8.x4.shared.b16 {%0,%1,%2,%3}, [%4];"
                 : "=r"(r0), "=r"(r1), "=r"(r2), "=r"(r3) : "r"(addr));
}

template <int EP>
__global__ __launch_bounds__(256)
void k_hgemm(const __half* __restrict__ A, const __half* __restrict__ Bt,
             void* __restrict__ Cv, int M, int N, int K,
             const float* __restrict__ aux) {
    extern __shared__ __half hsm[];

    int tid  = threadIdx.x;
    int warp = tid >> 5, lane = tid & 31;
    int wm = warp >> 2, wn = warp & 3;
    int g = lane >> 2, tig = lane & 3;
    int rowBase = blockIdx.x * HBM_;
    int colBase = blockIdx.y * HBN_;

    int crow = tid >> 1;
    int cseg = (tid & 1) * 16;
    const __half* Arow = A  + (size_t)(rowBase + crow) * K + cseg;
    const __half* Brow = Bt + (size_t)(colBase + crow) * K + cseg;

    int la_row = lane & 15;
    int la_col = (lane >> 4) << 3;
    int lb_row = (lane & 7) + ((lane & 16) >> 1);
    int lb_col = lane & 8;

    float acc[4][4][4];
#pragma unroll
    for (int mt = 0; mt < 4; mt++)
#pragma unroll
        for (int nt = 0; nt < 4; nt++)
#pragma unroll
            for (int e = 0; e < 4; e++) acc[mt][nt][e] = 0.f;

    auto load_tiles = [&](int k0, int buf) {
        __half* as = hsm + buf * HSTG;
        __half* bs = as + HAS;
        uint32_t ad = (uint32_t)__cvta_generic_to_shared(as + crow * HLD + cseg);
        uint32_t bd = (uint32_t)__cvta_generic_to_shared(bs + crow * HLD + cseg);
        cpa16(Arow + k0,     ad);
        cpa16(Arow + k0 + 8, ad + 16);
        cpa16(Brow + k0,     bd);
        cpa16(Brow + k0 + 8, bd + 16);
        asm volatile("cp.async.commit_group;" ::: "memory");
    };

    int NK = K / HBK_;
    load_tiles(0, 0);
    if (NK > 1) load_tiles(HBK_, 1);
    else        asm volatile("cp.async.commit_group;" ::: "memory");

    for (int it = 0; it < NK; it++) {
        if (it == NK - 1) asm volatile("cp.async.wait_group 0;" ::: "memory");
        else              asm volatile("cp.async.wait_group 1;" ::: "memory");
        __syncthreads();

        const __half* as = hsm + (it % 3) * HSTG;
        const __half* bs = as + HAS;
        uint32_t abase = (uint32_t)__cvta_generic_to_shared(as);
        uint32_t bbase = (uint32_t)__cvta_generic_to_shared(bs);

#pragma unroll
        for (int ks = 0; ks < 2; ks++) {
            int kb = ks * 16;
            uint32_t af[4][4];
#pragma unroll
            for (int mt = 0; mt < 4; mt++) {
                int r0 = wm * 64 + mt * 16;
                uint32_t addr = abase + ((r0 + la_row) * HLD + kb + la_col) * 2;
                ldsm4(af[mt][0], af[mt][1], af[mt][2], af[mt][3], addr);
            }
            uint32_t bf[4][2];
#pragma unroll
            for (int ntp = 0; ntp < 2; ntp++) {
                int c0 = wn * 32 + ntp * 16;
                uint32_t addr = bbase + ((c0 + lb_row) * HLD + kb + lb_col) * 2;
                ldsm4(bf[2 * ntp][0], bf[2 * ntp][1], bf[2 * ntp + 1][0], bf[2 * ntp + 1][1],
                      addr);
            }
#pragma unroll
            for (int mt = 0; mt < 4; mt++)
#pragma unroll
                for (int nt = 0; nt < 4; nt++) {
                    asm volatile(
                        "mma.sync.aligned.m16n8k16.row.col.f32.f16.f16.f32 "
                        "{%0,%1,%2,%3}, {%4,%5,%6,%7}, {%8,%9}, {%0,%1,%2,%3};"
                        : "+f"(acc[mt][nt][0]), "+f"(acc[mt][nt][1]),
                          "+f"(acc[mt][nt][2]), "+f"(acc[mt][nt][3])
                        : "r"(af[mt][0]), "r"(af[mt][1]), "r"(af[mt][2]), "r"(af[mt][3]),
                          "r"(bf[nt][0]), "r"(bf[nt][1]));
                }
        }
        __syncthreads();
        if (it + 2 < NK) load_tiles((it + 2) * HBK_, (it + 2) % 3);
    }

#pragma unroll
    for (int mt = 0; mt < 4; mt++) {
        int row = rowBase + wm * 64 + mt * 16 + g;
#pragma unroll
        for (int nt = 0; nt < 4; nt++) {
            int col = colBase + wn * 32 + nt * 8 + 2 * tig;
            float v0 = acc[mt][nt][0], v1 = acc[mt][nt][1];
            float v2 = acc[mt][nt][2], v3 = acc[mt][nt][3];
            if (EP == EP_BIAS) {
                float* C = (float*)Cv;
                v0 += aux[col]; v1 += aux[col + 1];
                v2 += aux[col]; v3 += aux[col + 1];
                __stcs((float2*)(C + (size_t)row * N + col),       make_float2(v0, v1));
                __stcs((float2*)(C + (size_t)(row + 8) * N + col), make_float2(v2, v3));
            } else if (EP == EP_BIAS_GELU_H) {
                __half* C = (__half*)Cv;
                v0 = gelu_f(v0 + aux[col]); v1 = gelu_f(v1 + aux[col + 1]);
                v2 = gelu_f(v2 + aux[col]); v3 = gelu_f(v3 + aux[col + 1]);
                *(__half2*)(C + (size_t)row * N + col)       = __floats2half2_rn(v0, v1);
                *(__half2*)(C + (size_t)(row + 8) * N + col) = __floats2half2_rn(v2, v3);
            } else if (EP == EP_RESADD) {      // + fp32 residual, fp32 out
                float* C = (float*)Cv;
                const float* r0p = aux + (size_t)row * N + col;
                const float* r1p = aux + (size_t)(row + 8) * N + col;
                v0 += r0p[0]; v1 += r0p[1];
                v2 += r1p[0]; v3 += r1p[1];
                *(float2*)(C + (size_t)row * N + col)       = make_float2(v0, v1);
                *(float2*)(C + (size_t)(row + 8) * N + col) = make_float2(v2, v3);
            } else {  // EP_QKV: elu+1 on cols<128 (Q,K), identity on V/pad, fp32 out
                float* C = (float*)Cv;
                if (col < 128) {
                    v0 = (v0 > 0.f) ? (v0 + 1.f) : __expf(v0);
                    v1 = (v1 > 0.f) ? (v1 + 1.f) : __expf(v1);
                    v2 = (v2 > 0.f) ? (v2 + 1.f) : __expf(v2);
                    v3 = (v3 > 0.f) ? (v3 + 1.f) : __expf(v3);
                }
                *(float2*)(C + (size_t)row * N + col)       = make_float2(v0, v1);
                *(float2*)(C + (size_t)(row + 8) * N + col) = make_float2(v2, v3);
            }
        }
    }
}

// ---------------- per-chunk KV / K-sum states (reads packed g_qkv) ----------------
__global__ void k_chunkstate() {
    int c = blockIdx.x, b = blockIdx.y;
    int base = b * SEQ + c * TCH;
    __shared__ float Ks[TCH][KD], Vs[TCH][KD];
    for (int i = threadIdx.x; i < TCH * KD; i += 256) {
        int t = i >> 6, d = i & 63;
        Ks[t][d] = g_qkv[(size_t)(base + t) * QKVW + 64 + d];
        Vs[t][d] = g_qkv[(size_t)(base + t) * QKVW + 128 + d];
    }
    __syncthreads();
    int sidx = b * NCH + c;
    for (int e = threadIdx.x; e < KD * KD; e += 256) {
        int a = e >> 6, v = e & 63;
        float s = 0.f;
#pragma unroll
        for (int t = 0; t < TCH; t++) s += Ks[t][a] * Vs[t][v];
        g_S[(size_t)sidx * KD * KD + e] = s;
    }
    if (threadIdx.x < KD) {
        float s = 0.f;
#pragma unroll
        for (int t = 0; t < TCH; t++) s += Ks[t][threadIdx.x];
        g_ks[sidx * KD + threadIdx.x] = s;
    }
}

// ---------------- fast exclusive prefix over chunks ----------------
__global__ void k_prefix() {
    int b = blockIdx.y;
    if (blockIdx.x < 128) {
        __shared__ float st[NCH][32];
        int i0 = blockIdx.x * 32;
        int t = threadIdx.x;
        int c = t >> 5, il = t & 31;
        for (int cc = c; cc < NCH; cc += 8)
            st[cc][il] = g_S[(size_t)(b * NCH + cc) * (KD * KD) + i0 + il];
        __syncthreads();
        if (t < 32) {
            float run = 0.f;
            for (int cc = 0; cc < NCH; cc++) {
                float v = st[cc][t];
                st[cc][t] = run;
                run += v;
            }
        }
        __syncthreads();
        for (int cc = c; cc < NCH; cc += 8)
            g_Sp[(size_t)(b * NCH + cc) * (KD * KD) + i0 + il] = st[cc][il];
    } else if (threadIdx.x < KD) {
        float run = 0.f;
        for (int c = 0; c < NCH; c++) {
            int off = (b * NCH + c) * KD + threadIdx.x;
            g_ksp[off] = run;
            run += g_ks[off];
        }
    }
}

// ---------------- intra + inter chunk attention (fp16 output) ----------------
__global__ __launch_bounds__(256) void k_attn() {
    int c = blockIdx.x, b = blockIdx.y;
    int base = b * SEQ + c * TCH;
    int sidx = b * NCH + c;
    __shared__ float Qs[TCH][KD], Ks[TCH][KD], Vs[TCH][KD];
    __shared__ float Sp[KD][KD];
    __shared__ float sc[TCH][TCH];
    __shared__ float dens[TCH];
    __shared__ float ksp[KD];

    for (int i = threadIdx.x; i < TCH * KD; i += 256) {
        int t = i >> 6, d = i & 63;
        Qs[t][d] = g_qkv[(size_t)(base + t) * QKVW + d];
        Ks[t][d] = g_qkv[(size_t)(base + t) * QKVW + 64 + d];
        Vs[t][d] = g_qkv[(size_t)(base + t) * QKVW + 128 + d];
    }
    for (int i = threadIdx.x; i < KD * KD; i += 256)
        Sp[i >> 6][i & 63] = g_Sp[(size_t)sidx * KD * KD + i];
    if (threadIdx.x < KD) ksp[threadIdx.x] = g_ksp[sidx * KD + threadIdx.x];
    __syncthreads();

    for (int e = threadIdx.x; e < TCH * TCH; e += 256) {
        int t = e / TCH, s = e % TCH;
        float v = 0.f;
        if (s <= t) {
#pragma unroll
            for (int k = 0; k < KD; k++) v += Qs[t][k] * Ks[s][k];
        }
        sc[t][s] = v;
    }
    __syncthreads();

    if (threadIdx.x < TCH) {
        int t = threadIdx.x;
        float d = 0.f;
        for (int s = 0; s <= t; s++) d += sc[t][s];
#pragma unroll
        for (int k = 0; k < KD; k++) d += Qs[t][k] * ksp[k];
        dens[t] = d + 1e-6f;
    }
    __syncthreads();

    for (int e = threadIdx.x; e < TCH * KD; e += 256) {
        int t = e >> 6, j = e & 63;
        float v = 0.f;
#pragma unroll
        for (int s = 0; s < TCH; s++) v += sc[t][s] * Vs[s][j];
#pragma unroll
        for (int k = 0; k < KD; k++) v += Qs[t][k] * Sp[k][j];
        g_attnh[(size_t)(base + t) * KD + j] = __float2half(v / dens[t]);
    }
}

// ---------------- one-pass LayerNorm: optional fp32 out + fp16 out ----------------
__global__ void k_ln2(const float* __restrict__ in, const float* __restrict__ g,
                      const float* __restrict__ b, float* __restrict__ outf,
                      __half* __restrict__ outh) {
    int r = blockIdx.x;
    int t = threadIdx.x;                      // 256 threads, 4 elems each
    float4 v = ((const float4*)(in + (size_t)r * DIM))[t];
    float s = v.x + v.y + v.z + v.w;
    float q = v.x * v.x + v.y * v.y + v.z * v.z + v.w * v.w;
#pragma unroll
    for (int o = 16; o > 0; o >>= 1) {
        s += __shfl_xor_sync(0xFFFFFFFFu, s, o);
        q += __shfl_xor_sync(0xFFFFFFFFu, q, o);
    }
    __shared__ float ss[8], qq[8];
    if ((t & 31) == 0) { ss[t >> 5] = s; qq[t >> 5] = q; }
    __syncthreads();
    if (t < 32) {
        float s2 = (t < 8) ? ss[t] : 0.f;
        float q2 = (t < 8) ? qq[t] : 0.f;
#pragma unroll
        for (int o = 4; o > 0; o >>= 1) {
            s2 += __shfl_xor_sync(0xFFFFFFFFu, s2, o);
            q2 += __shfl_xor_sync(0xFFFFFFFFu, q2, o);
        }
        if (t == 0) { ss[0] = s2; qq[0] = q2; }
    }
    __syncthreads();
    float mean = ss[0] * (1.f / DIM);
    float var  = qq[0] * (1.f / DIM) - mean * mean;
    float rstd = rsqrtf(var + 1e-5f);

    float4 gv = ((const float4*)g)[t];
    float4 bv = ((const float4*)b)[t];
    float4 o;
    o.x = (v.x - mean) * rstd * gv.x + bv.x;
    o.y = (v.y - mean) * rstd * gv.y + bv.y;
    o.z = (v.z - mean) * rstd * gv.z + bv.z;
    o.w = (v.w - mean) * rstd * gv.w + bv.w;
    if (outf) ((float4*)(outf + (size_t)r * DIM))[t] = o;
    __half* oh = outh + (size_t)r * DIM + 4 * t;
    *(__half2*)(oh)     = __floats2half2_rn(o.x, o.y);
    *(__half2*)(oh + 2) = __floats2half2_rn(o.z, o.w);
}

// ---------------- launch ----------------
extern "C" void kernel_launch(void* const* d_in, const int* in_sizes, int n_in,
                              void* d_out, int out_size) {
    const int*   idx = (const int*)d_in[0];
    const float* tok = (const float*)d_in[1];
    const float* pos = (const float*)d_in[2];
    const float* Wq  = (const float*)d_in[3];
    const float* Wk  = (const float*)d_in[4];
    const float* Wv  = (const float*)d_in[5];
    const float* Wo  = (const float*)d_in[6];
    const float* ng  = (const float*)d_in[7];
    const float* nb  = (const float*)d_in[8];
    const float* og  = (const float*)d_in[9];
    const float* ob  = (const float*)d_in[10];
    const float* W1  = (const float*)d_in[11];
    const float* b1  = (const float*)d_in[12];
    const float* W2  = (const float*)d_in[13];
    const float* b2  = (const float*)d_in[14];
    float* out = (float*)d_out;

    float *px, *py, *pqkv;
    __half *pah, *pxh, *phh, *pw1t, *pw2t, *pwot, *pwqkvt;
    cudaGetSymbolAddress((void**)&px,  g_x);
    cudaGetSymbolAddress((void**)&py,  g_y);
    cudaGetSymbolAddress((void**)&pqkv, g_qkv);
    cudaGetSymbolAddress((void**)&pah, g_attnh);
    cudaGetSymbolAddress((void**)&pxh, g_xh);
    cudaGetSymbolAddress((void**)&phh, g_hh);
    cudaGetSymbolAddress((void**)&pw1t, g_w1t);
    cudaGetSymbolAddress((void**)&pw2t, g_w2t);
    cudaGetSymbolAddress((void**)&pwot, g_wot);
    cudaGetSymbolAddress((void**)&pwqkvt, g_wqkvt);

    cudaFuncSetAttribute(k_hgemm<EP_BIAS>, cudaFuncAttributeMaxDynamicSharedMemorySize, HSMEM_BYTES);
    cudaFuncSetAttribute(k_hgemm<EP_BIAS_GELU_H>, cudaFuncAttributeMaxDynamicSharedMemorySize, HSMEM_BYTES);
    cudaFuncSetAttribute(k_hgemm<EP_QKV>, cudaFuncAttributeMaxDynamicSharedMemorySize, HSMEM_BYTES);
    cudaFuncSetAttribute(k_hgemm<EP_RESADD>, cudaFuncAttributeMaxDynamicSharedMemorySize, HSMEM_BYTES);

    // one-time weight transposes+converts (graph nodes)
    k_transcvt<<<dim3(HID / 32, DIM / 32), dim3(32, 8)>>>(W1, pw1t, DIM, HID);
    k_transcvt<<<dim3(VOCAB / 32, HID / 32), dim3(32, 8)>>>(W2, pw2t, HID, VOCAB);
    k_transcvt_small<<<dim3(64, 1, NH * 4), dim3(32, 8)>>>(Wq, Wk, Wv, Wo);

    k_embed<<<MTOT, 256>>>(idx, tok, pos);

    for (int layer = 0; layer < NH; layer++) {
        // QKV = x(fp16) @ packed W^T  [fp16 mma; elu+1 fused for Q,K]
        k_hgemm<EP_QKV><<<dim3(MTOT / HBM_, QKVW / HBN_), 256, HSMEM_BYTES>>>(
            pxh, pwqkvt + (size_t)layer * QKVW * DIM, pqkv, MTOT, QKVW, DIM, nullptr);
        k_chunkstate<<<dim3(NCH, BATCH), 256>>>();
        k_prefix<<<dim3(129, BATCH), 256>>>();
        k_attn<<<dim3(NCH, BATCH), 256>>>();

        // y = attn @ Wo + x  [fp16 mma, fp32 residual + out]
        k_hgemm<EP_RESADD><<<dim3(MTOT / HBM_, DIM / HBN_), 256, HSMEM_BYTES>>>(
            pah, pwot + (size_t)layer * DIM * KD, py, MTOT, DIM, KD, px);
        // x = LN(y), fp32 + fp16
        k_ln2<<<MTOT, 256>>>(py, ng + layer * DIM, nb + layer * DIM, px, pxh);
    }

    // final LN (fp16 only; fp32 output dead)
    k_ln2<<<MTOT, 256>>>(px, og, ob, nullptr, pxh);
    // h = gelu(xn @ W1 + b1)  [fp16 mma, fp16 output]
    k_hgemm<EP_BIAS_GELU_H><<<dim3(MTOT / HBM_, HID / HBN_), 256, HSMEM_BYTES>>>(
        pxh, pw1t, phh, MTOT, HID, DIM, b1);
    // logits = h @ W2 + b2    [fp16 mma, fp32 streaming output]
    k_hgemm<EP_BIAS><<<dim3(MTOT / HBM_, VOCAB / HBN_), 256, HSMEM_BYTES>>>(
        phh, pw2t, out, MTOT, VOCAB, HID, b2);
}